// round 2
// baseline (speedup 1.0000x reference)
#include <cuda_runtime.h>

#define NN   20000
#define EE   320000
#define MM   3
#define IN_  128
#define HH   4
#define DD   64
#define HD_  256
#define HID_ 128

// ---------------- scratch (static device globals; no allocation) ----------------
__device__ float g_feat[(size_t)MM * NN * HD_];   // per-metapath projected features
__device__ float g_z[(size_t)MM * NN * HD_];      // per-metapath GAT outputs
__device__ float g_el[MM * NN * HH];
__device__ float g_er[MM * NN * HH];
__device__ int   g_cnt[MM * NN];
__device__ int   g_off[MM * (NN + 1)];
__device__ int   g_cur[MM * NN];
__device__ int   g_esrc[MM * EE];
__device__ float g_wsum[MM];
__device__ float g_beta[MM];

// ---------------- K0: zero accumulators (must run every graph replay) ----------------
__global__ void k_zero() {
    int i = blockIdx.x * blockDim.x + threadIdx.x;
    if (i < MM * NN) g_cnt[i] = 0;
    if (i < MM) g_wsum[i] = 0.0f;
}

// ---------------- K1: feat[m] = h @ W[m]   (BM=64,BN=64,K=128 in 2 chunks) ----------------
__global__ void k_gemm_feat(const float* __restrict__ h, const float* __restrict__ W) {
    const int m    = blockIdx.z;
    const int row0 = blockIdx.x * 64;
    const int col0 = blockIdx.y * 64;
    __shared__ float As[64][68];
    __shared__ float Bs[64][68];
    const int tid = threadIdx.x;
    const int tx = tid & 15, ty = tid >> 4;

    float acc[4][4];
#pragma unroll
    for (int i = 0; i < 4; i++)
#pragma unroll
        for (int j = 0; j < 4; j++) acc[i][j] = 0.0f;

    const float4* hv = (const float4*)h;
    const float4* Wv = (const float4*)W + (size_t)m * (IN_ * HD_ / 4);

    for (int kc = 0; kc < 2; kc++) {
        // load A chunk: 64 rows x 64 k  (transposed into As[k][row])
#pragma unroll
        for (int i = tid; i < 64 * 16; i += 256) {
            int r = i >> 4, k4 = i & 15;
            int gr = row0 + r;
            float4 v = make_float4(0.f, 0.f, 0.f, 0.f);
            if (gr < NN) v = hv[gr * 32 + kc * 16 + k4];
            As[k4 * 4 + 0][r] = v.x;
            As[k4 * 4 + 1][r] = v.y;
            As[k4 * 4 + 2][r] = v.z;
            As[k4 * 4 + 3][r] = v.w;
        }
        // load B chunk: 64 k x 64 cols
#pragma unroll
        for (int i = tid; i < 64 * 16; i += 256) {
            int k = i >> 4, c4 = i & 15;
            float4 v = Wv[(kc * 64 + k) * (HD_ / 4) + (col0 >> 2) + c4];
            *(float4*)&Bs[k][c4 * 4] = v;
        }
        __syncthreads();
#pragma unroll 8
        for (int k = 0; k < 64; k++) {
            float4 a = *(const float4*)&As[k][ty * 4];
            float4 b = *(const float4*)&Bs[k][tx * 4];
            float av[4] = {a.x, a.y, a.z, a.w};
            float bv[4] = {b.x, b.y, b.z, b.w};
#pragma unroll
            for (int i = 0; i < 4; i++)
#pragma unroll
                for (int j = 0; j < 4; j++) acc[i][j] = fmaf(av[i], bv[j], acc[i][j]);
        }
        __syncthreads();
    }
#pragma unroll
    for (int i = 0; i < 4; i++) {
        int gr = row0 + ty * 4 + i;
        if (gr < NN) {
            float4 v = make_float4(acc[i][0], acc[i][1], acc[i][2], acc[i][3]);
            *(float4*)&g_feat[((size_t)m * NN + gr) * HD_ + col0 + tx * 4] = v;
        }
    }
}

// ---------------- K2: el/er = per-head dot(feat, attn)  (1 warp per (m,n)) ----------------
__global__ void k_elr(const float* __restrict__ attn_l, const float* __restrict__ attn_r) {
    int gw = (blockIdx.x * blockDim.x + threadIdx.x) >> 5;
    int lane = threadIdx.x & 31;
    if (gw >= MM * NN) return;
    int m = gw / NN, n = gw - m * NN;
    const float4* f = (const float4*)&g_feat[((size_t)m * NN + n) * HD_];
    int hh = lane >> 3, s = lane & 7;            // 8 lanes per head
    float4 fa = f[hh * 16 + s * 2];
    float4 fb = f[hh * 16 + s * 2 + 1];
    const float4* al = (const float4*)&attn_l[(m * HH + hh) * DD];
    const float4* ar = (const float4*)&attn_r[(m * HH + hh) * DD];
    float4 la = al[s * 2], lb = al[s * 2 + 1];
    float4 ra = ar[s * 2], rb = ar[s * 2 + 1];
    float pl = fa.x * la.x + fa.y * la.y + fa.z * la.z + fa.w * la.w +
               fb.x * lb.x + fb.y * lb.y + fb.z * lb.z + fb.w * lb.w;
    float pr = fa.x * ra.x + fa.y * ra.y + fa.z * ra.z + fa.w * ra.w +
               fb.x * rb.x + fb.y * rb.y + fb.z * rb.z + fb.w * rb.w;
#pragma unroll
    for (int o = 4; o; o >>= 1) {
        pl += __shfl_down_sync(0xffffffffu, pl, o);
        pr += __shfl_down_sync(0xffffffffu, pr, o);
    }
    if (s == 0) {
        g_el[(m * NN + n) * HH + hh] = pl;
        g_er[(m * NN + n) * HH + hh] = pr;
    }
}

// ---------------- K3: histogram of dst ----------------
__global__ void k_hist(const int* __restrict__ dst) {
    int i = blockIdx.x * blockDim.x + threadIdx.x;
    if (i >= MM * EE) return;
    int m = i / EE;
    atomicAdd(&g_cnt[m * NN + dst[i]], 1);
}

// ---------------- K4: exclusive prefix sum per metapath (1 block each) ----------------
__global__ void k_scan() {
    int m = blockIdx.x;
    __shared__ int sums[512];
    int t = threadIdx.x;
    const int CH = (NN + 511) / 512;   // 40
    int base = t * CH;
    int s = 0;
    for (int i = 0; i < CH; i++) {
        int idx = base + i;
        if (idx < NN) s += g_cnt[m * NN + idx];
    }
    sums[t] = s;
    __syncthreads();
    for (int off = 1; off < 512; off <<= 1) {
        int v = (t >= off) ? sums[t - off] : 0;
        __syncthreads();
        sums[t] += v;
        __syncthreads();
    }
    int run = t ? sums[t - 1] : 0;
    for (int i = 0; i < CH; i++) {
        int idx = base + i;
        if (idx < NN) {
            g_off[m * (NN + 1) + idx] = run;
            g_cur[m * NN + idx] = run;
            run += g_cnt[m * NN + idx];
        }
    }
    if (t == 511) g_off[m * (NN + 1) + NN] = sums[511];
}

// ---------------- K5: scatter edges into CSR ----------------
__global__ void k_scatter(const int* __restrict__ src, const int* __restrict__ dst) {
    int i = blockIdx.x * blockDim.x + threadIdx.x;
    if (i >= MM * EE) return;
    int m = i / EE;
    int p = atomicAdd(&g_cur[m * NN + dst[i]], 1);
    g_esrc[(size_t)m * EE + p] = src[i];
}

// ---------------- K6: edge softmax + aggregation (1 warp per (m,n)), z = out + bias ----
__global__ void k_agg(const float* __restrict__ bias) {
    int gw = (blockIdx.x * blockDim.x + threadIdx.x) >> 5;
    int lane = threadIdx.x & 31;
    if (gw >= MM * NN) return;
    int m = gw / NN, n = gw - m * NN;
    int start = g_off[m * (NN + 1) + n];
    int end   = g_off[m * (NN + 1) + n + 1];
    float4 er4 = *(const float4*)&g_er[(size_t)(m * NN + n) * HH];
    const int* esrc = &g_esrc[(size_t)m * EE];

    // pass A: per-head sum of exp(leaky_relu(el[s]+er[n]))
    float s0 = 0.f, s1 = 0.f, s2 = 0.f, s3 = 0.f;
    for (int e = start + lane; e < end; e += 32) {
        int s = esrc[e];
        float4 el4 = *(const float4*)&g_el[(size_t)(m * NN + s) * HH];
        float e0 = el4.x + er4.x; e0 = e0 > 0.f ? e0 : 0.2f * e0; s0 += __expf(e0);
        float e1 = el4.y + er4.y; e1 = e1 > 0.f ? e1 : 0.2f * e1; s1 += __expf(e1);
        float e2 = el4.z + er4.z; e2 = e2 > 0.f ? e2 : 0.2f * e2; s2 += __expf(e2);
        float e3 = el4.w + er4.w; e3 = e3 > 0.f ? e3 : 0.2f * e3; s3 += __expf(e3);
    }
#pragma unroll
    for (int o = 16; o; o >>= 1) {
        s0 += __shfl_xor_sync(0xffffffffu, s0, o);
        s1 += __shfl_xor_sync(0xffffffffu, s1, o);
        s2 += __shfl_xor_sync(0xffffffffu, s2, o);
        s3 += __shfl_xor_sync(0xffffffffu, s3, o);
    }
    float rd0 = 1.f / fmaxf(s0, 1e-9f);
    float rd1 = 1.f / fmaxf(s1, 1e-9f);
    float rd2 = 1.f / fmaxf(s2, 1e-9f);
    float rd3 = 1.f / fmaxf(s3, 1e-9f);

    // lane owns channels [4*lane..4*lane+3] (head A) and [128+4*lane..] (head B)
    bool hi = (lane & 16) != 0;
    float erA = hi ? er4.y : er4.x;
    float erB = hi ? er4.w : er4.z;
    float rdA = hi ? rd1 : rd0;
    float rdB = hi ? rd3 : rd2;

    float4 accA = make_float4(0.f, 0.f, 0.f, 0.f);
    float4 accB = make_float4(0.f, 0.f, 0.f, 0.f);
    const float4* featv = (const float4*)g_feat;

    for (int j = start; j < end; j += 32) {
        int myE = j + lane;
        int smy = (myE < end) ? esrc[myE] : 0;
        int cnt = min(32, end - j);
        for (int t = 0; t < cnt; t++) {
            int s = __shfl_sync(0xffffffffu, smy, t);
            float4 el4 = *(const float4*)&g_el[(size_t)(m * NN + s) * HH];
            float eA = (hi ? el4.y : el4.x) + erA;
            float eB = (hi ? el4.w : el4.z) + erB;
            eA = eA > 0.f ? eA : 0.2f * eA;
            eB = eB > 0.f ? eB : 0.2f * eB;
            float wA = __expf(eA) * rdA;
            float wB = __expf(eB) * rdB;
            const float4* frow = featv + ((size_t)m * NN + s) * (HD_ / 4);
            float4 fa = frow[lane];
            float4 fb = frow[lane + 32];
            accA.x = fmaf(wA, fa.x, accA.x); accA.y = fmaf(wA, fa.y, accA.y);
            accA.z = fmaf(wA, fa.z, accA.z); accA.w = fmaf(wA, fa.w, accA.w);
            accB.x = fmaf(wB, fb.x, accB.x); accB.y = fmaf(wB, fb.y, accB.y);
            accB.z = fmaf(wB, fb.z, accB.z); accB.w = fmaf(wB, fb.w, accB.w);
        }
    }
    const float4* bv = (const float4*)&bias[m * HD_];
    float4 ba = bv[lane], bb = bv[lane + 32];
    float4* zrow = (float4*)&g_z[((size_t)m * NN + n) * HD_];
    zrow[lane]      = make_float4(accA.x + ba.x, accA.y + ba.y, accA.z + ba.z, accA.w + ba.w);
    zrow[lane + 32] = make_float4(accB.x + bb.x, accB.y + bb.y, accB.z + bb.z, accB.w + bb.w);
}

// ---------------- K7: semantic GEMM + tanh + dot(W2), reduce mean into g_wsum ----------
__global__ void k_sem(const float* __restrict__ W1, const float* __restrict__ b1,
                      const float* __restrict__ W2) {
    const int m    = blockIdx.y;
    const int row0 = blockIdx.x * 64;
    __shared__ float As[32][68];
    __shared__ float Bs[32][132];
    __shared__ float red[16][16][4];
    __shared__ float rowsum[16];
    const int tid = threadIdx.x;
    const int tx = tid & 15, ty = tid >> 4;   // cols tx*8..+7, rows ty*4..+3

    float acc[4][8];
#pragma unroll
    for (int i = 0; i < 4; i++)
#pragma unroll
        for (int j = 0; j < 8; j++) acc[i][j] = 0.0f;

    const float4* zv = (const float4*)&g_z[(size_t)m * NN * HD_];
    const float4* w1v = (const float4*)W1;

    for (int kc = 0; kc < 8; kc++) {   // K=256 in chunks of 32
        // A: 64 rows x 32 k (transposed)
#pragma unroll
        for (int i = tid; i < 64 * 8; i += 256) {
            int r = i >> 3, k4 = i & 7;
            int gr = row0 + r;
            float4 v = make_float4(0.f, 0.f, 0.f, 0.f);
            if (gr < NN) v = zv[gr * (HD_ / 4) + kc * 8 + k4];
            As[k4 * 4 + 0][r] = v.x;
            As[k4 * 4 + 1][r] = v.y;
            As[k4 * 4 + 2][r] = v.z;
            As[k4 * 4 + 3][r] = v.w;
        }
        // B: 32 k x 128 cols
#pragma unroll
        for (int i = tid; i < 32 * 32; i += 256) {
            int k = i >> 5, c4 = i & 31;
            float4 v = w1v[(kc * 32 + k) * (HID_ / 4) + c4];
            *(float4*)&Bs[k][c4 * 4] = v;
        }
        __syncthreads();
#pragma unroll 4
        for (int k = 0; k < 32; k++) {
            float4 a  = *(const float4*)&As[k][ty * 4];
            float4 b0 = *(const float4*)&Bs[k][tx * 8];
            float4 b1f = *(const float4*)&Bs[k][tx * 8 + 4];
            float av[4] = {a.x, a.y, a.z, a.w};
            float bvv[8] = {b0.x, b0.y, b0.z, b0.w, b1f.x, b1f.y, b1f.z, b1f.w};
#pragma unroll
            for (int i = 0; i < 4; i++)
#pragma unroll
                for (int j = 0; j < 8; j++) acc[i][j] = fmaf(av[i], bvv[j], acc[i][j]);
        }
        __syncthreads();
    }

    float b1loc[8], w2loc[8];
#pragma unroll
    for (int j = 0; j < 8; j++) {
        b1loc[j] = b1[tx * 8 + j];
        w2loc[j] = W2[tx * 8 + j];
    }
#pragma unroll
    for (int i = 0; i < 4; i++) {
        float p = 0.f;
#pragma unroll
        for (int j = 0; j < 8; j++) p += tanhf(acc[i][j] + b1loc[j]) * w2loc[j];
        red[ty][tx][i] = p;
    }
    __syncthreads();
    if (tx == 0) {
        float tot = 0.f;
        for (int i = 0; i < 4; i++) {
            int gr = row0 + ty * 4 + i;
            if (gr < NN) {
                float s = 0.f;
                for (int x = 0; x < 16; x++) s += red[ty][x][i];
                tot += s;
            }
        }
        rowsum[ty] = tot;
    }
    __syncthreads();
    if (tid == 0) {
        float t = 0.f;
        for (int y = 0; y < 16; y++) t += rowsum[y];
        atomicAdd(&g_wsum[m], t);
    }
}

// ---------------- K8: beta = softmax(mean_n w) ----------------
__global__ void k_beta() {
    float w0 = g_wsum[0] / (float)NN;
    float w1 = g_wsum[1] / (float)NN;
    float w2 = g_wsum[2] / (float)NN;
    float mx = fmaxf(w0, fmaxf(w1, w2));
    float e0 = __expf(w0 - mx), e1 = __expf(w1 - mx), e2 = __expf(w2 - mx);
    float s = e0 + e1 + e2;
    g_beta[0] = e0 / s;
    g_beta[1] = e1 / s;
    g_beta[2] = e2 / s;
}

// ---------------- K9: out = sum_m beta[m] * z[m] ----------------
__global__ void k_comb(float* __restrict__ out) {
    int i = blockIdx.x * blockDim.x + threadIdx.x;
    const int TOT = NN * HD_ / 4;
    if (i >= TOT) return;
    float b0 = g_beta[0], b1 = g_beta[1], b2 = g_beta[2];
    const float4* z = (const float4*)g_z;
    const size_t S = (size_t)NN * (HD_ / 4);
    float4 a = z[i], b = z[S + i], c = z[2 * S + i];
    ((float4*)out)[i] = make_float4(b0 * a.x + b1 * b.x + b2 * c.x,
                                    b0 * a.y + b1 * b.y + b2 * c.y,
                                    b0 * a.z + b1 * b.z + b2 * c.z,
                                    b0 * a.w + b1 * b.w + b2 * c.w);
}

// ---------------- launcher ----------------
extern "C" void kernel_launch(void* const* d_in, const int* in_sizes, int n_in,
                              void* d_out, int out_size) {
    const float* h    = (const float*)d_in[0];
    const int*   src  = (const int*)d_in[1];
    const int*   dst  = (const int*)d_in[2];
    const float* W    = (const float*)d_in[3];
    const float* al   = (const float*)d_in[4];
    const float* ar   = (const float*)d_in[5];
    const float* bias = (const float*)d_in[6];
    const float* sW1  = (const float*)d_in[7];
    const float* sb1  = (const float*)d_in[8];
    const float* sW2  = (const float*)d_in[9];
    float* out = (float*)d_out;

    k_zero<<<(MM * NN + 255) / 256, 256>>>();

    dim3 g1((NN + 63) / 64, HD_ / 64, MM);
    k_gemm_feat<<<g1, 256>>>(h, W);

    k_elr<<<(MM * NN * 32 + 255) / 256, 256>>>(al, ar);

    k_hist<<<(MM * EE + 255) / 256, 256>>>(dst);
    k_scan<<<MM, 512>>>();
    k_scatter<<<(MM * EE + 255) / 256, 256>>>(src, dst);

    k_agg<<<(MM * NN * 32 + 255) / 256, 256>>>(bias);

    dim3 g6((NN + 63) / 64, MM);
    k_sem<<<g6, 256>>>(sW1, sb1, sW2);
    k_beta<<<1, 1>>>();
    k_comb<<<(NN * HD_ / 4 + 255) / 256, 256>>>(out);
}

// round 6
// speedup vs baseline: 1.3426x; 1.3426x over previous
#include <cuda_runtime.h>
#include <cuda_bf16.h>
#include <cstdint>

#define NN   20000
#define EE   320000
#define MM   3
#define IN_  128
#define HH   4
#define DD   64
#define HD_  256
#define HID_ 128

// ================= scratch (static device globals; no allocation) =================
__device__ __align__(16) float g_feat[(size_t)MM * NN * HD_];
__device__ __align__(16) float g_z[(size_t)MM * NN * HD_];
__device__ __align__(16) __nv_bfloat16 g_zhi[(size_t)MM * NN * HD_];
__device__ __align__(16) __nv_bfloat16 g_zlo[(size_t)MM * NN * HD_];
__device__ __align__(16) __nv_bfloat16 g_hhi[(size_t)NN * IN_];
__device__ __align__(16) __nv_bfloat16 g_hlo[(size_t)NN * IN_];
__device__ __align__(16) __nv_bfloat16 g_Whi[(size_t)MM * HD_ * IN_];   // [m][n][k]  (W^T, k-contig)
__device__ __align__(16) __nv_bfloat16 g_Wlo[(size_t)MM * HD_ * IN_];
__device__ __align__(16) __nv_bfloat16 g_W1hi[(size_t)HID_ * HD_];      // [n][k]
__device__ __align__(16) __nv_bfloat16 g_W1lo[(size_t)HID_ * HD_];
__device__ __align__(16) float g_el[MM * NN * HH];
__device__ __align__(16) float g_er[MM * NN * HH];
__device__ int   g_cnt[MM * NN];
__device__ int   g_off[MM * (NN + 1)];
__device__ int   g_cur[MM * NN];
__device__ int   g_esrc[MM * EE];
__device__ float g_wsum[MM];
__device__ float g_beta[MM];

// ================= HMMA helper (plain sm_80+ mma.sync — no 'a' features) =================
#define MMA_BF16(c, a0, a1, a2, a3, b0, b1) \
    asm volatile("mma.sync.aligned.m16n8k16.row.col.f32.bf16.bf16.f32 " \
                 "{%0,%1,%2,%3}, {%4,%5,%6,%7}, {%8,%9}, {%0,%1,%2,%3};" \
                 : "+f"((c)[0]), "+f"((c)[1]), "+f"((c)[2]), "+f"((c)[3]) \
                 : "r"(a0), "r"(a1), "r"(a2), "r"(a3), "r"(b0), "r"(b1))

// One K-sweep of a 128x128 CTA tile: 8 warps as 4x2 (warp tile 32x64).
// A in smem [128 rows][PITCHW words] k-contig; B in smem [128 n][PITCHW words] k-contig.
// PITCHW % 32 == 4 -> fragment loads are bank-conflict-free.
template <int PITCHW, int NK>
__device__ __forceinline__ void gemm_pass(const uint32_t* __restrict__ A,
                                          const uint32_t* __restrict__ B,
                                          float acc[2][8][4], int warpM0, int warpN0,
                                          int g, int tg) {
#pragma unroll
    for (int kk = 0; kk < NK; kk++) {
        const int kw = kk * 8 + tg;
        uint32_t a[2][4];
#pragma unroll
        for (int mf = 0; mf < 2; mf++) {
            const int rb = (warpM0 + mf * 16 + g) * PITCHW + kw;
            a[mf][0] = A[rb];
            a[mf][1] = A[rb + 8 * PITCHW];
            a[mf][2] = A[rb + 4];
            a[mf][3] = A[rb + 8 * PITCHW + 4];
        }
#pragma unroll
        for (int nf = 0; nf < 8; nf++) {
            const int nb = (warpN0 + nf * 8 + g) * PITCHW + kw;
            const uint32_t b0 = B[nb];
            const uint32_t b1 = B[nb + 4];
            MMA_BF16(acc[0][nf], a[0][0], a[0][1], a[0][2], a[0][3], b0, b1);
            MMA_BF16(acc[1][nf], a[1][0], a[1][1], a[1][2], a[1][3], b0, b1);
        }
    }
}

// ================= K0: zero accumulators =================
__global__ void k_zero() {
    int i = blockIdx.x * blockDim.x + threadIdx.x;
    if (i < MM * NN) g_cnt[i] = 0;
    if (i < MM) g_wsum[i] = 0.0f;
}

// ================= conversions: fp32 -> bf16 hi/lo =================
__global__ void k_conv_h(const float* __restrict__ h) {
    int i = blockIdx.x * blockDim.x + threadIdx.x;
    if (i >= NN * IN_) return;
    float x = h[i];
    __nv_bfloat16 hi = __float2bfloat16(x);
    g_hhi[i] = hi;
    g_hlo[i] = __float2bfloat16(x - __bfloat162float(hi));
}
__global__ void k_conv_W(const float* __restrict__ W) {
    int i = blockIdx.x * blockDim.x + threadIdx.x;
    if (i >= MM * IN_ * HD_) return;
    int m = i / (IN_ * HD_);
    int r = i - m * (IN_ * HD_);
    int k = r / HD_, n = r - (r / HD_) * HD_;
    float x = W[i];
    __nv_bfloat16 hi = __float2bfloat16(x);
    size_t o = (size_t)m * HD_ * IN_ + (size_t)n * IN_ + k;
    g_Whi[o] = hi;
    g_Wlo[o] = __float2bfloat16(x - __bfloat162float(hi));
}
__global__ void k_conv_W1(const float* __restrict__ W1) {
    int i = blockIdx.x * blockDim.x + threadIdx.x;
    if (i >= HD_ * HID_) return;
    int k = i / HID_, n = i - (i / HID_) * HID_;
    float x = W1[i];
    __nv_bfloat16 hi = __float2bfloat16(x);
    size_t o = (size_t)n * HD_ + k;
    g_W1hi[o] = hi;
    g_W1lo[o] = __float2bfloat16(x - __bfloat162float(hi));
}

// ================= K1: feat = h @ W  (HMMA, hi/lo x3)  grid (157, 2, 3) ===============
// smem (words): AHI @0, ALO @8704, BHI @17408, BLO @26112  (pitch 68 words = 136 bf16)
#define F_PITCH 68
#define F_ALO   8704
#define F_BHI   17408
#define F_BLO   26112
#define F_SMEM_BYTES (4 * 128 * F_PITCH * 4)   // 139264

__global__ void __launch_bounds__(256, 1) k_mma_feat() {
    extern __shared__ uint32_t smw[];
    const int m = blockIdx.z;
    const int row0 = blockIdx.x * 128;
    const int ncol0 = blockIdx.y * 128;
    const int tid = threadIdx.x;
    const int lane = tid & 31, warp = tid >> 5;
    const int g = lane >> 2, tg = lane & 3;
    const int warpM0 = (warp & 3) * 32;
    const int warpN0 = (warp >> 2) * 64;

    // ---- load tiles (each thread: one (row, half), 8 uint4 per region) ----
    {
        const int r = tid >> 1, half = tid & 1;
        uint4* dAH = (uint4*)smw;
        uint4* dAL = (uint4*)(smw + F_ALO);
        uint4* dBH = (uint4*)(smw + F_BHI);
        uint4* dBL = (uint4*)(smw + F_BLO);
        const int db = r * 17 + half * 8;          // 68 words = 17 uint4 per row
        const int gr = row0 + r;
        if (gr < NN) {
            const uint4* sh = (const uint4*)g_hhi + (size_t)gr * 16 + half * 8;
            const uint4* sl = (const uint4*)g_hlo + (size_t)gr * 16 + half * 8;
#pragma unroll
            for (int j = 0; j < 8; j++) { dAH[db + j] = sh[j]; dAL[db + j] = sl[j]; }
        } else {
            uint4 zz = make_uint4(0u, 0u, 0u, 0u);
#pragma unroll
            for (int j = 0; j < 8; j++) { dAH[db + j] = zz; dAL[db + j] = zz; }
        }
        const uint4* wh = (const uint4*)g_Whi + ((size_t)m * HD_ + ncol0 + r) * 16 + half * 8;
        const uint4* wl = (const uint4*)g_Wlo + ((size_t)m * HD_ + ncol0 + r) * 16 + half * 8;
#pragma unroll
        for (int j = 0; j < 8; j++) { dBH[db + j] = wh[j]; dBL[db + j] = wl[j]; }
    }
    __syncthreads();

    float acc[2][8][4];
#pragma unroll
    for (int i = 0; i < 2; i++)
#pragma unroll
        for (int j = 0; j < 8; j++)
#pragma unroll
            for (int q = 0; q < 4; q++) acc[i][j][q] = 0.0f;

    gemm_pass<F_PITCH, 8>(smw, smw + F_BHI, acc, warpM0, warpN0, g, tg);          // AH*BH
    gemm_pass<F_PITCH, 8>(smw, smw + F_BLO, acc, warpM0, warpN0, g, tg);          // AH*BL
    gemm_pass<F_PITCH, 8>(smw + F_ALO, smw + F_BHI, acc, warpM0, warpN0, g, tg);  // AL*BH

    // ---- epilogue: store feat ----
#pragma unroll
    for (int mf = 0; mf < 2; mf++) {
        const int grow = row0 + warpM0 + mf * 16 + g;
#pragma unroll
        for (int nf = 0; nf < 8; nf++) {
            const int gcol = ncol0 + warpN0 + nf * 8 + tg * 2;
            if (grow < NN)
                *(float2*)&g_feat[((size_t)m * NN + grow) * HD_ + gcol] =
                    make_float2(acc[mf][nf][0], acc[mf][nf][1]);
            if (grow + 8 < NN)
                *(float2*)&g_feat[((size_t)m * NN + grow + 8) * HD_ + gcol] =
                    make_float2(acc[mf][nf][2], acc[mf][nf][3]);
        }
    }
}

// ================= K2: el/er = per-head dot(feat, attn)  (1 warp per (m,n)) ============
__global__ void k_elr(const float* __restrict__ attn_l, const float* __restrict__ attn_r) {
    int gw = (blockIdx.x * blockDim.x + threadIdx.x) >> 5;
    int lane = threadIdx.x & 31;
    if (gw >= MM * NN) return;
    int m = gw / NN, n = gw - m * NN;
    const float4* f = (const float4*)&g_feat[((size_t)m * NN + n) * HD_];
    int hh = lane >> 3, s = lane & 7;
    float4 fa = f[hh * 16 + s * 2];
    float4 fb = f[hh * 16 + s * 2 + 1];
    const float4* al = (const float4*)&attn_l[(m * HH + hh) * DD];
    const float4* ar = (const float4*)&attn_r[(m * HH + hh) * DD];
    float4 la = al[s * 2], lb = al[s * 2 + 1];
    float4 ra = ar[s * 2], rb = ar[s * 2 + 1];
    float pl = fa.x * la.x + fa.y * la.y + fa.z * la.z + fa.w * la.w +
               fb.x * lb.x + fb.y * lb.y + fb.z * lb.z + fb.w * lb.w;
    float pr = fa.x * ra.x + fa.y * ra.y + fa.z * ra.z + fa.w * ra.w +
               fb.x * rb.x + fb.y * rb.y + fb.z * rb.z + fb.w * rb.w;
#pragma unroll
    for (int o = 4; o; o >>= 1) {
        pl += __shfl_down_sync(0xffffffffu, pl, o);
        pr += __shfl_down_sync(0xffffffffu, pr, o);
    }
    if (s == 0) {
        g_el[(m * NN + n) * HH + hh] = pl;
        g_er[(m * NN + n) * HH + hh] = pr;
    }
}

// ================= K3-K5: CSR build =================
__global__ void k_hist(const int* __restrict__ dst) {
    int i = blockIdx.x * blockDim.x + threadIdx.x;
    if (i >= MM * EE) return;
    int m = i / EE;
    atomicAdd(&g_cnt[m * NN + dst[i]], 1);
}
__global__ void k_scan() {
    int m = blockIdx.x;
    __shared__ int sums[512];
    int t = threadIdx.x;
    const int CH = (NN + 511) / 512;
    int base = t * CH;
    int s = 0;
    for (int i = 0; i < CH; i++) {
        int idx = base + i;
        if (idx < NN) s += g_cnt[m * NN + idx];
    }
    sums[t] = s;
    __syncthreads();
    for (int off = 1; off < 512; off <<= 1) {
        int v = (t >= off) ? sums[t - off] : 0;
        __syncthreads();
        sums[t] += v;
        __syncthreads();
    }
    int run = t ? sums[t - 1] : 0;
    for (int i = 0; i < CH; i++) {
        int idx = base + i;
        if (idx < NN) {
            g_off[m * (NN + 1) + idx] = run;
            g_cur[m * NN + idx] = run;
            run += g_cnt[m * NN + idx];
        }
    }
    if (t == 511) g_off[m * (NN + 1) + NN] = sums[511];
}
__global__ void k_scatter(const int* __restrict__ src, const int* __restrict__ dst) {
    int i = blockIdx.x * blockDim.x + threadIdx.x;
    if (i >= MM * EE) return;
    int m = i / EE;
    int p = atomicAdd(&g_cur[m * NN + dst[i]], 1);
    g_esrc[(size_t)m * EE + p] = src[i];
}

// ================= K6: edge softmax + aggregation; writes z (fp32 + bf16 hi/lo) ========
__global__ void k_agg(const float* __restrict__ bias) {
    int gw = (blockIdx.x * blockDim.x + threadIdx.x) >> 5;
    int lane = threadIdx.x & 31;
    if (gw >= MM * NN) return;
    int m = gw / NN, n = gw - m * NN;
    int start = g_off[m * (NN + 1) + n];
    int end   = g_off[m * (NN + 1) + n + 1];
    float4 er4 = *(const float4*)&g_er[(size_t)(m * NN + n) * HH];
    const int* esrc = &g_esrc[(size_t)m * EE];

    float s0 = 0.f, s1 = 0.f, s2 = 0.f, s3 = 0.f;
    for (int e = start + lane; e < end; e += 32) {
        int s = esrc[e];
        float4 el4 = *(const float4*)&g_el[(size_t)(m * NN + s) * HH];
        float e0 = el4.x + er4.x; e0 = e0 > 0.f ? e0 : 0.2f * e0; s0 += __expf(e0);
        float e1 = el4.y + er4.y; e1 = e1 > 0.f ? e1 : 0.2f * e1; s1 += __expf(e1);
        float e2 = el4.z + er4.z; e2 = e2 > 0.f ? e2 : 0.2f * e2; s2 += __expf(e2);
        float e3 = el4.w + er4.w; e3 = e3 > 0.f ? e3 : 0.2f * e3; s3 += __expf(e3);
    }
#pragma unroll
    for (int o = 16; o; o >>= 1) {
        s0 += __shfl_xor_sync(0xffffffffu, s0, o);
        s1 += __shfl_xor_sync(0xffffffffu, s1, o);
        s2 += __shfl_xor_sync(0xffffffffu, s2, o);
        s3 += __shfl_xor_sync(0xffffffffu, s3, o);
    }
    float rd0 = 1.f / fmaxf(s0, 1e-9f);
    float rd1 = 1.f / fmaxf(s1, 1e-9f);
    float rd2 = 1.f / fmaxf(s2, 1e-9f);
    float rd3 = 1.f / fmaxf(s3, 1e-9f);

    bool hi = (lane & 16) != 0;
    float4 accA = make_float4(0.f, 0.f, 0.f, 0.f);
    float4 accB = make_float4(0.f, 0.f, 0.f, 0.f);
    const float4* featv = (const float4*)g_feat;

    for (int j = start; j < end; j += 32) {
        int myE = j + lane;
        int cnt = min(32, end - j);
        int smy = (myE < end) ? esrc[myE] : 0;
        float4 el4 = *(const float4*)&g_el[(size_t)(m * NN + smy) * HH];
        float e0 = el4.x + er4.x; e0 = e0 > 0.f ? e0 : 0.2f * e0;
        float e1 = el4.y + er4.y; e1 = e1 > 0.f ? e1 : 0.2f * e1;
        float e2 = el4.z + er4.z; e2 = e2 > 0.f ? e2 : 0.2f * e2;
        float e3 = el4.w + er4.w; e3 = e3 > 0.f ? e3 : 0.2f * e3;
        float w0my = __expf(e0) * rd0;
        float w1my = __expf(e1) * rd1;
        float w2my = __expf(e2) * rd2;
        float w3my = __expf(e3) * rd3;
        for (int t = 0; t < cnt; t++) {
            int s = __shfl_sync(0xffffffffu, smy, t);
            float b0 = __shfl_sync(0xffffffffu, w0my, t);
            float b1 = __shfl_sync(0xffffffffu, w1my, t);
            float b2 = __shfl_sync(0xffffffffu, w2my, t);
            float b3 = __shfl_sync(0xffffffffu, w3my, t);
            float wA = hi ? b1 : b0;
            float wB = hi ? b3 : b2;
            const float4* frow = featv + ((size_t)m * NN + s) * (HD_ / 4);
            float4 fa = frow[lane];
            float4 fb = frow[lane + 32];
            accA.x = fmaf(wA, fa.x, accA.x); accA.y = fmaf(wA, fa.y, accA.y);
            accA.z = fmaf(wA, fa.z, accA.z); accA.w = fmaf(wA, fa.w, accA.w);
            accB.x = fmaf(wB, fb.x, accB.x); accB.y = fmaf(wB, fb.y, accB.y);
            accB.z = fmaf(wB, fb.z, accB.z); accB.w = fmaf(wB, fb.w, accB.w);
        }
    }
    const float4* bv = (const float4*)&bias[m * HD_];
    float4 ba = bv[lane], bb = bv[lane + 32];
    float oA[4] = {accA.x + ba.x, accA.y + ba.y, accA.z + ba.z, accA.w + ba.w};
    float oB[4] = {accB.x + bb.x, accB.y + bb.y, accB.z + bb.z, accB.w + bb.w};
    size_t zb = ((size_t)m * NN + n) * HD_;
    *(float4*)&g_z[zb + 4 * lane]       = make_float4(oA[0], oA[1], oA[2], oA[3]);
    *(float4*)&g_z[zb + 128 + 4 * lane] = make_float4(oB[0], oB[1], oB[2], oB[3]);
    __nv_bfloat16 hA[4], lA[4], hB[4], lB[4];
#pragma unroll
    for (int q = 0; q < 4; q++) {
        hA[q] = __float2bfloat16(oA[q]);
        lA[q] = __float2bfloat16(oA[q] - __bfloat162float(hA[q]));
        hB[q] = __float2bfloat16(oB[q]);
        lB[q] = __float2bfloat16(oB[q] - __bfloat162float(hB[q]));
    }
    *(uint2*)&g_zhi[zb + 4 * lane]       = *(uint2*)hA;
    *(uint2*)&g_zhi[zb + 128 + 4 * lane] = *(uint2*)hB;
    *(uint2*)&g_zlo[zb + 4 * lane]       = *(uint2*)lA;
    *(uint2*)&g_zlo[zb + 128 + 4 * lane] = *(uint2*)lB;
}

// ================= K7: semantic GEMM (HMMA) + fused tanh/W2/mean  grid (157, 1, 3) ====
// smem regions of 128 rows x 132 words (pitch 132 words = 264 bf16):
// S0 @0 : Ahi   S1 @16896 : W1hi   S2 @33792 : W1lo, later overwritten by Alo
#define S_PITCH 132
#define S_S1    16896
#define S_S2    33792
#define S_SMEM_BYTES (3 * 128 * S_PITCH * 4)   // 202752

__global__ void __launch_bounds__(256, 1) k_mma_sem(const float* __restrict__ b1,
                                                    const float* __restrict__ W2) {
    extern __shared__ uint32_t smw[];
    __shared__ float sB1[HID_], sW2[HID_], sred[8];
    const int m = blockIdx.z;
    const int row0 = blockIdx.x * 128;
    const int tid = threadIdx.x;
    const int lane = tid & 31, warp = tid >> 5;
    const int g = lane >> 2, tg = lane & 3;
    const int warpM0 = (warp & 3) * 32;
    const int warpN0 = (warp >> 2) * 64;

    if (tid < HID_) { sB1[tid] = b1[tid]; sW2[tid] = W2[tid]; }

    const int r = tid >> 1, half = tid & 1;
    const int db = r * 33 + half * 16;             // 132 words = 33 uint4 per row
    const int gr = row0 + r;
    // A hi  +  W1 hi/lo
    {
        uint4* dA = (uint4*)smw;
        uint4* dB1h = (uint4*)(smw + S_S1);
        uint4* dB1l = (uint4*)(smw + S_S2);
        if (gr < NN) {
            const uint4* sh = (const uint4*)g_zhi + ((size_t)m * NN + gr) * 32 + half * 16;
#pragma unroll
            for (int j = 0; j < 16; j++) dA[db + j] = sh[j];
        } else {
            uint4 zz = make_uint4(0u, 0u, 0u, 0u);
#pragma unroll
            for (int j = 0; j < 16; j++) dA[db + j] = zz;
        }
        const uint4* w1h = (const uint4*)g_W1hi + (size_t)r * 32 + half * 16;
        const uint4* w1l = (const uint4*)g_W1lo + (size_t)r * 32 + half * 16;
#pragma unroll
        for (int j = 0; j < 16; j++) { dB1h[db + j] = w1h[j]; dB1l[db + j] = w1l[j]; }
    }
    __syncthreads();

    float acc[2][8][4];
#pragma unroll
    for (int i = 0; i < 2; i++)
#pragma unroll
        for (int j = 0; j < 8; j++)
#pragma unroll
            for (int q = 0; q < 4; q++) acc[i][j][q] = 0.0f;

    gemm_pass<S_PITCH, 16>(smw, smw + S_S1, acc, warpM0, warpN0, g, tg);   // AH * W1H
    gemm_pass<S_PITCH, 16>(smw, smw + S_S2, acc, warpM0, warpN0, g, tg);   // AH * W1L
    __syncthreads();
    // overwrite S2 with A-lo
    {
        uint4* dA = (uint4*)(smw + S_S2);
        if (gr < NN) {
            const uint4* sl = (const uint4*)g_zlo + ((size_t)m * NN + gr) * 32 + half * 16;
#pragma unroll
            for (int j = 0; j < 16; j++) dA[db + j] = sl[j];
        } else {
            uint4 zz = make_uint4(0u, 0u, 0u, 0u);
#pragma unroll
            for (int j = 0; j < 16; j++) dA[db + j] = zz;
        }
    }
    __syncthreads();
    gemm_pass<S_PITCH, 16>(smw + S_S2, smw + S_S1, acc, warpM0, warpN0, g, tg);  // AL * W1H

    // ---- fused epilogue: p = sum tanh(acc + b1) * W2 over this thread's elements ----
    float p = 0.f;
#pragma unroll
    for (int mf = 0; mf < 2; mf++) {
        const int grow = row0 + warpM0 + mf * 16 + g;
        const bool v0 = grow < NN, v1 = grow + 8 < NN;
#pragma unroll
        for (int nf = 0; nf < 8; nf++) {
            const int col = warpN0 + nf * 8 + tg * 2;
            if (v0) {
                p = fmaf(tanhf(acc[mf][nf][0] + sB1[col]),     sW2[col],     p);
                p = fmaf(tanhf(acc[mf][nf][1] + sB1[col + 1]), sW2[col + 1], p);
            }
            if (v1) {
                p = fmaf(tanhf(acc[mf][nf][2] + sB1[col]),     sW2[col],     p);
                p = fmaf(tanhf(acc[mf][nf][3] + sB1[col + 1]), sW2[col + 1], p);
            }
        }
    }
#pragma unroll
    for (int o = 16; o; o >>= 1) p += __shfl_xor_sync(0xffffffffu, p, o);
    if (lane == 0) sred[warp] = p;
    __syncthreads();
    if (tid == 0) {
        float t = 0.f;
#pragma unroll
        for (int w = 0; w < 8; w++) t += sred[w];
        atomicAdd(&g_wsum[m], t);
    }
}

// ================= K8/K9: beta + combine =================
__global__ void k_beta() {
    float w0 = g_wsum[0] / (float)NN;
    float w1 = g_wsum[1] / (float)NN;
    float w2 = g_wsum[2] / (float)NN;
    float mx = fmaxf(w0, fmaxf(w1, w2));
    float e0 = __expf(w0 - mx), e1 = __expf(w1 - mx), e2 = __expf(w2 - mx);
    float s = e0 + e1 + e2;
    g_beta[0] = e0 / s;
    g_beta[1] = e1 / s;
    g_beta[2] = e2 / s;
}
__global__ void k_comb(float* __restrict__ out) {
    int i = blockIdx.x * blockDim.x + threadIdx.x;
    const int TOT = NN * HD_ / 4;
    if (i >= TOT) return;
    float b0 = g_beta[0], b1 = g_beta[1], b2 = g_beta[2];
    const float4* z = (const float4*)g_z;
    const size_t S = (size_t)NN * (HD_ / 4);
    float4 a = z[i], b = z[S + i], c = z[2 * S + i];
    ((float4*)out)[i] = make_float4(b0 * a.x + b1 * b.x + b2 * c.x,
                                    b0 * a.y + b1 * b.y + b2 * c.y,
                                    b0 * a.z + b1 * b.z + b2 * c.z,
                                    b0 * a.w + b1 * b.w + b2 * c.w);
}

// ================= launcher =================
extern "C" void kernel_launch(void* const* d_in, const int* in_sizes, int n_in,
                              void* d_out, int out_size) {
    const float* h    = (const float*)d_in[0];
    const int*   src  = (const int*)d_in[1];
    const int*   dst  = (const int*)d_in[2];
    const float* W    = (const float*)d_in[3];
    const float* al   = (const float*)d_in[4];
    const float* ar   = (const float*)d_in[5];
    const float* bias = (const float*)d_in[6];
    const float* sW1  = (const float*)d_in[7];
    const float* sb1  = (const float*)d_in[8];
    const float* sW2  = (const float*)d_in[9];
    float* out = (float*)d_out;

    cudaFuncSetAttribute(k_mma_feat, cudaFuncAttributeMaxDynamicSharedMemorySize, F_SMEM_BYTES);
    cudaFuncSetAttribute(k_mma_sem, cudaFuncAttributeMaxDynamicSharedMemorySize, S_SMEM_BYTES);

    const int NTILES = (NN + 127) / 128;   // 157

    k_zero<<<(MM * NN + 255) / 256, 256>>>();
    k_conv_h<<<(NN * IN_ + 255) / 256, 256>>>(h);
    k_conv_W<<<(MM * IN_ * HD_ + 255) / 256, 256>>>(W);
    k_conv_W1<<<(HD_ * HID_ + 255) / 256, 256>>>(sW1);
    k_hist<<<(MM * EE + 255) / 256, 256>>>(dst);

    dim3 gf(NTILES, 2, MM);
    k_mma_feat<<<gf, 256, F_SMEM_BYTES>>>();

    k_elr<<<(MM * NN * 32 + 255) / 256, 256>>>(al, ar);
    k_scan<<<MM, 512>>>();
    k_scatter<<<(MM * EE + 255) / 256, 256>>>(src, dst);
    k_agg<<<(MM * NN * 32 + 255) / 256, 256>>>(bias);

    dim3 gs(NTILES, 1, MM);
    k_mma_sem<<<gs, 256, S_SMEM_BYTES>>>(sb1, sW2);
    k_beta<<<1, 1>>>();
    k_comb<<<(NN * HD_ / 4 + 255) / 256, 256>>>(out);
}

// round 7
// speedup vs baseline: 1.6615x; 1.2375x over previous
#include <cuda_runtime.h>
#include <cuda_bf16.h>
#include <cstdint>

#define NN   20000
#define EE   320000
#define MM   3
#define IN_  128
#define HH   4
#define DD   64
#define HD_  256
#define HID_ 128

// ================= scratch (static device globals; no allocation) =================
__device__ __align__(16) float g_feat[(size_t)MM * NN * HD_];
__device__ __align__(16) float g_z[(size_t)MM * NN * HD_];
__device__ __align__(16) __nv_bfloat16 g_zhi[(size_t)MM * NN * HD_];
__device__ __align__(16) __nv_bfloat16 g_hhi[(size_t)NN * IN_];
__device__ __align__(16) __nv_bfloat16 g_hlo[(size_t)NN * IN_];
__device__ __align__(16) __nv_bfloat16 g_Whi[(size_t)MM * HD_ * IN_];   // [m][n][k]  (W^T, k-contig)
__device__ __align__(16) __nv_bfloat16 g_Wlo[(size_t)MM * HD_ * IN_];
__device__ __align__(16) __nv_bfloat16 g_W1hi[(size_t)HID_ * HD_];      // [n][k]
__device__ __align__(16) float g_el[MM * NN * HH];
__device__ __align__(16) float g_er[MM * NN * HH];
__device__ int   g_cnt[MM * NN];
__device__ int   g_off[MM * (NN + 1)];
__device__ int   g_cur[MM * NN];
__device__ int   g_esrc[MM * EE];
__device__ float g_wsum[MM];

// ================= HMMA helper (plain sm_80+ mma.sync — no 'a' features) =================
#define MMA_BF16(c, a0, a1, a2, a3, b0, b1) \
    asm volatile("mma.sync.aligned.m16n8k16.row.col.f32.bf16.bf16.f32 " \
                 "{%0,%1,%2,%3}, {%4,%5,%6,%7}, {%8,%9}, {%0,%1,%2,%3};" \
                 : "+f"((c)[0]), "+f"((c)[1]), "+f"((c)[2]), "+f"((c)[3]) \
                 : "r"(a0), "r"(a1), "r"(a2), "r"(a3), "r"(b0), "r"(b1))

// One K-sweep of a 128x128 CTA tile: 8 warps as 4x2 (warp tile 32x64).
// A in smem [128 rows][PITCHW words] k-contig; B in smem [128 n][PITCHW words] k-contig.
// PITCHW % 32 == 4 -> fragment loads are bank-conflict-free.
template <int PITCHW, int NK>
__device__ __forceinline__ void gemm_pass(const uint32_t* __restrict__ A,
                                          const uint32_t* __restrict__ B,
                                          float acc[2][8][4], int warpM0, int warpN0,
                                          int g, int tg) {
#pragma unroll
    for (int kk = 0; kk < NK; kk++) {
        const int kw = kk * 8 + tg;
        uint32_t a[2][4];
#pragma unroll
        for (int mf = 0; mf < 2; mf++) {
            const int rb = (warpM0 + mf * 16 + g) * PITCHW + kw;
            a[mf][0] = A[rb];
            a[mf][1] = A[rb + 8 * PITCHW];
            a[mf][2] = A[rb + 4];
            a[mf][3] = A[rb + 8 * PITCHW + 4];
        }
#pragma unroll
        for (int nf = 0; nf < 8; nf++) {
            const int nb = (warpN0 + nf * 8 + g) * PITCHW + kw;
            const uint32_t b0 = B[nb];
            const uint32_t b1 = B[nb + 4];
            MMA_BF16(acc[0][nf], a[0][0], a[0][1], a[0][2], a[0][3], b0, b1);
            MMA_BF16(acc[1][nf], a[1][0], a[1][1], a[1][2], a[1][3], b0, b1);
        }
    }
}

// ================= K0: fused prep — zero counters + all fp32->bf16 conversions =========
__global__ void k_prep(const float* __restrict__ h, const float* __restrict__ W,
                       const float* __restrict__ W1) {
    int i = blockIdx.x * blockDim.x + threadIdx.x;
    if (i < NN * IN_) {
        float x = h[i];
        __nv_bfloat16 hi = __float2bfloat16(x);
        g_hhi[i] = hi;
        g_hlo[i] = __float2bfloat16(x - __bfloat162float(hi));
    }
    if (i < MM * IN_ * HD_) {
        int m = i / (IN_ * HD_);
        int r = i - m * (IN_ * HD_);
        int k = r / HD_, n = r - (r / HD_) * HD_;
        float x = W[i];
        __nv_bfloat16 hi = __float2bfloat16(x);
        size_t o = (size_t)m * HD_ * IN_ + (size_t)n * IN_ + k;
        g_Whi[o] = hi;
        g_Wlo[o] = __float2bfloat16(x - __bfloat162float(hi));
    }
    if (i < HD_ * HID_) {
        int k = i / HID_, n = i - (i / HID_) * HID_;
        g_W1hi[(size_t)n * HD_ + k] = __float2bfloat16(W1[i]);
    }
    if (i < MM * NN) g_cnt[i] = 0;
    if (i < MM) g_wsum[i] = 0.0f;
}

// ================= K1: feat = h @ W (HMMA hi/lo x3) + FUSED el/er  grid (157, 2, 3) ====
// smem (words): AHI @0, ALO @8704, BHI @17408, BLO @26112  (pitch 68 words = 136 bf16)
#define F_PITCH 68
#define F_ALO   8704
#define F_BHI   17408
#define F_BLO   26112
#define F_SMEM_BYTES (4 * 128 * F_PITCH * 4)   // 139264

__global__ void __launch_bounds__(256, 1) k_mma_feat(const float* __restrict__ attn_l,
                                                     const float* __restrict__ attn_r) {
    extern __shared__ uint32_t smw[];
    __shared__ float sAL[128], sAR[128];
    const int m = blockIdx.z;
    const int row0 = blockIdx.x * 128;
    const int ncol0 = blockIdx.y * 128;
    const int tid = threadIdx.x;
    const int lane = tid & 31, warp = tid >> 5;
    const int g = lane >> 2, tg = lane & 3;
    const int warpM0 = (warp & 3) * 32;
    const int warpN0 = (warp >> 2) * 64;

    if (tid < 128) {
        sAL[tid] = attn_l[m * HD_ + ncol0 + tid];
        sAR[tid] = attn_r[m * HD_ + ncol0 + tid];
    }

    // ---- load tiles (each thread: one (row, half), 8 uint4 per region) ----
    {
        const int r = tid >> 1, half = tid & 1;
        uint4* dAH = (uint4*)smw;
        uint4* dAL = (uint4*)(smw + F_ALO);
        uint4* dBH = (uint4*)(smw + F_BHI);
        uint4* dBL = (uint4*)(smw + F_BLO);
        const int db = r * 17 + half * 8;          // 68 words = 17 uint4 per row
        const int gr = row0 + r;
        if (gr < NN) {
            const uint4* sh = (const uint4*)g_hhi + (size_t)gr * 16 + half * 8;
            const uint4* sl = (const uint4*)g_hlo + (size_t)gr * 16 + half * 8;
#pragma unroll
            for (int j = 0; j < 8; j++) { dAH[db + j] = sh[j]; dAL[db + j] = sl[j]; }
        } else {
            uint4 zz = make_uint4(0u, 0u, 0u, 0u);
#pragma unroll
            for (int j = 0; j < 8; j++) { dAH[db + j] = zz; dAL[db + j] = zz; }
        }
        const uint4* wh = (const uint4*)g_Whi + ((size_t)m * HD_ + ncol0 + r) * 16 + half * 8;
        const uint4* wl = (const uint4*)g_Wlo + ((size_t)m * HD_ + ncol0 + r) * 16 + half * 8;
#pragma unroll
        for (int j = 0; j < 8; j++) { dBH[db + j] = wh[j]; dBL[db + j] = wl[j]; }
    }
    __syncthreads();

    float acc[2][8][4];
#pragma unroll
    for (int i = 0; i < 2; i++)
#pragma unroll
        for (int j = 0; j < 8; j++)
#pragma unroll
            for (int q = 0; q < 4; q++) acc[i][j][q] = 0.0f;

    gemm_pass<F_PITCH, 8>(smw, smw + F_BHI, acc, warpM0, warpN0, g, tg);          // AH*BH
    gemm_pass<F_PITCH, 8>(smw, smw + F_BLO, acc, warpM0, warpN0, g, tg);          // AH*BL
    gemm_pass<F_PITCH, 8>(smw + F_ALO, smw + F_BHI, acc, warpM0, warpN0, g, tg);  // AL*BH

    // ---- epilogue: store feat + fused per-head el/er partial dots ----
    // this warp's 64 cols == one head: head = 2*blockIdx.y + (warp>>2)
    float pl[4] = {0.f, 0.f, 0.f, 0.f};     // rows warpM0+g + {0,8,16,24}
    float pr[4] = {0.f, 0.f, 0.f, 0.f};
#pragma unroll
    for (int mf = 0; mf < 2; mf++) {
        const int grow = row0 + warpM0 + mf * 16 + g;
#pragma unroll
        for (int nf = 0; nf < 8; nf++) {
            const int lc = warpN0 + nf * 8 + tg * 2;
            const int gcol = ncol0 + lc;
            if (grow < NN)
                *(float2*)&g_feat[((size_t)m * NN + grow) * HD_ + gcol] =
                    make_float2(acc[mf][nf][0], acc[mf][nf][1]);
            if (grow + 8 < NN)
                *(float2*)&g_feat[((size_t)m * NN + grow + 8) * HD_ + gcol] =
                    make_float2(acc[mf][nf][2], acc[mf][nf][3]);
            pl[mf * 2]     += acc[mf][nf][0] * sAL[lc] + acc[mf][nf][1] * sAL[lc + 1];
            pl[mf * 2 + 1] += acc[mf][nf][2] * sAL[lc] + acc[mf][nf][3] * sAL[lc + 1];
            pr[mf * 2]     += acc[mf][nf][0] * sAR[lc] + acc[mf][nf][1] * sAR[lc + 1];
            pr[mf * 2 + 1] += acc[mf][nf][2] * sAR[lc] + acc[mf][nf][3] * sAR[lc + 1];
        }
    }
    // reduce over the quad (lanes tg=0..3 share g)
#pragma unroll
    for (int s = 0; s < 4; s++) {
        pl[s] += __shfl_xor_sync(0xffffffffu, pl[s], 1);
        pl[s] += __shfl_xor_sync(0xffffffffu, pl[s], 2);
        pr[s] += __shfl_xor_sync(0xffffffffu, pr[s], 1);
        pr[s] += __shfl_xor_sync(0xffffffffu, pr[s], 2);
    }
    if (tg == 0) {
        const int head = 2 * blockIdx.y + (warp >> 2);
#pragma unroll
        for (int s = 0; s < 4; s++) {
            const int grow = row0 + warpM0 + g + s * 8;
            if (grow < NN) {
                g_el[(size_t)(m * NN + grow) * HH + head] = pl[s];
                g_er[(size_t)(m * NN + grow) * HH + head] = pr[s];
            }
        }
    }
}

// ================= K2-K4: CSR build =================
__global__ void k_hist(const int* __restrict__ dst) {
    int i = blockIdx.x * blockDim.x + threadIdx.x;
    if (i >= MM * EE) return;
    int m = i / EE;
    atomicAdd(&g_cnt[m * NN + dst[i]], 1);
}
__global__ void k_scan() {
    int m = blockIdx.x;
    __shared__ int sums[512];
    int t = threadIdx.x;
    const int CH = (NN + 511) / 512;
    int base = t * CH;
    int s = 0;
    for (int i = 0; i < CH; i++) {
        int idx = base + i;
        if (idx < NN) s += g_cnt[m * NN + idx];
    }
    sums[t] = s;
    __syncthreads();
    for (int off = 1; off < 512; off <<= 1) {
        int v = (t >= off) ? sums[t - off] : 0;
        __syncthreads();
        sums[t] += v;
        __syncthreads();
    }
    int run = t ? sums[t - 1] : 0;
    for (int i = 0; i < CH; i++) {
        int idx = base + i;
        if (idx < NN) {
            g_off[m * (NN + 1) + idx] = run;
            g_cur[m * NN + idx] = run;
            run += g_cnt[m * NN + idx];
        }
    }
    if (t == 511) g_off[m * (NN + 1) + NN] = sums[511];
}
__global__ void k_scatter(const int* __restrict__ src, const int* __restrict__ dst) {
    int i = blockIdx.x * blockDim.x + threadIdx.x;
    if (i >= MM * EE) return;
    int m = i / EE;
    int p = atomicAdd(&g_cur[m * NN + dst[i]], 1);
    g_esrc[(size_t)m * EE + p] = src[i];
}

// ================= K5: edge softmax + aggregation; writes z (fp32 + bf16) ==============
__global__ void k_agg(const float* __restrict__ bias) {
    int gw = (blockIdx.x * blockDim.x + threadIdx.x) >> 5;
    int lane = threadIdx.x & 31;
    if (gw >= MM * NN) return;
    int m = gw / NN, n = gw - m * NN;
    int start = g_off[m * (NN + 1) + n];
    int end   = g_off[m * (NN + 1) + n + 1];
    float4 er4 = *(const float4*)&g_er[(size_t)(m * NN + n) * HH];
    const int* esrc = &g_esrc[(size_t)m * EE];

    float s0 = 0.f, s1 = 0.f, s2 = 0.f, s3 = 0.f;
    for (int e = start + lane; e < end; e += 32) {
        int s = esrc[e];
        float4 el4 = *(const float4*)&g_el[(size_t)(m * NN + s) * HH];
        float e0 = el4.x + er4.x; e0 = e0 > 0.f ? e0 : 0.2f * e0; s0 += __expf(e0);
        float e1 = el4.y + er4.y; e1 = e1 > 0.f ? e1 : 0.2f * e1; s1 += __expf(e1);
        float e2 = el4.z + er4.z; e2 = e2 > 0.f ? e2 : 0.2f * e2; s2 += __expf(e2);
        float e3 = el4.w + er4.w; e3 = e3 > 0.f ? e3 : 0.2f * e3; s3 += __expf(e3);
    }
#pragma unroll
    for (int o = 16; o; o >>= 1) {
        s0 += __shfl_xor_sync(0xffffffffu, s0, o);
        s1 += __shfl_xor_sync(0xffffffffu, s1, o);
        s2 += __shfl_xor_sync(0xffffffffu, s2, o);
        s3 += __shfl_xor_sync(0xffffffffu, s3, o);
    }
    float rd0 = 1.f / fmaxf(s0, 1e-9f);
    float rd1 = 1.f / fmaxf(s1, 1e-9f);
    float rd2 = 1.f / fmaxf(s2, 1e-9f);
    float rd3 = 1.f / fmaxf(s3, 1e-9f);

    bool hi = (lane & 16) != 0;
    float4 accA = make_float4(0.f, 0.f, 0.f, 0.f);
    float4 accB = make_float4(0.f, 0.f, 0.f, 0.f);
    const float4* featv = (const float4*)g_feat;

    for (int j = start; j < end; j += 32) {
        int myE = j + lane;
        int cnt = min(32, end - j);
        int smy = (myE < end) ? esrc[myE] : 0;
        float4 el4 = *(const float4*)&g_el[(size_t)(m * NN + smy) * HH];
        float e0 = el4.x + er4.x; e0 = e0 > 0.f ? e0 : 0.2f * e0;
        float e1 = el4.y + er4.y; e1 = e1 > 0.f ? e1 : 0.2f * e1;
        float e2 = el4.z + er4.z; e2 = e2 > 0.f ? e2 : 0.2f * e2;
        float e3 = el4.w + er4.w; e3 = e3 > 0.f ? e3 : 0.2f * e3;
        float w0my = __expf(e0) * rd0;
        float w1my = __expf(e1) * rd1;
        float w2my = __expf(e2) * rd2;
        float w3my = __expf(e3) * rd3;
        for (int t = 0; t < cnt; t++) {
            int s = __shfl_sync(0xffffffffu, smy, t);
            float b0 = __shfl_sync(0xffffffffu, w0my, t);
            float b1 = __shfl_sync(0xffffffffu, w1my, t);
            float b2 = __shfl_sync(0xffffffffu, w2my, t);
            float b3 = __shfl_sync(0xffffffffu, w3my, t);
            float wA = hi ? b1 : b0;
            float wB = hi ? b3 : b2;
            const float4* frow = featv + ((size_t)m * NN + s) * (HD_ / 4);
            float4 fa = frow[lane];
            float4 fb = frow[lane + 32];
            accA.x = fmaf(wA, fa.x, accA.x); accA.y = fmaf(wA, fa.y, accA.y);
            accA.z = fmaf(wA, fa.z, accA.z); accA.w = fmaf(wA, fa.w, accA.w);
            accB.x = fmaf(wB, fb.x, accB.x); accB.y = fmaf(wB, fb.y, accB.y);
            accB.z = fmaf(wB, fb.z, accB.z); accB.w = fmaf(wB, fb.w, accB.w);
        }
    }
    const float4* bv = (const float4*)&bias[m * HD_];
    float4 ba = bv[lane], bb = bv[lane + 32];
    float oA[4] = {accA.x + ba.x, accA.y + ba.y, accA.z + ba.z, accA.w + ba.w};
    float oB[4] = {accB.x + bb.x, accB.y + bb.y, accB.z + bb.z, accB.w + bb.w};
    size_t zb = ((size_t)m * NN + n) * HD_;
    *(float4*)&g_z[zb + 4 * lane]       = make_float4(oA[0], oA[1], oA[2], oA[3]);
    *(float4*)&g_z[zb + 128 + 4 * lane] = make_float4(oB[0], oB[1], oB[2], oB[3]);
    __nv_bfloat16 hA[4], hB[4];
#pragma unroll
    for (int q = 0; q < 4; q++) {
        hA[q] = __float2bfloat16(oA[q]);
        hB[q] = __float2bfloat16(oB[q]);
    }
    *(uint2*)&g_zhi[zb + 4 * lane]       = *(uint2*)hA;
    *(uint2*)&g_zhi[zb + 128 + 4 * lane] = *(uint2*)hB;
}

// ================= K6: semantic GEMM (HMMA, single bf16 pass) + fused epilogue =========
// smem regions of 128 rows x 132 words: S0 @0 : A(zhi)   S1 @16896 : W1hi
#define S_PITCH 132
#define S_S1    16896
#define S_SMEM_BYTES (2 * 128 * S_PITCH * 4)   // 135168

__global__ void __launch_bounds__(256, 1) k_mma_sem(const float* __restrict__ b1,
                                                    const float* __restrict__ W2) {
    extern __shared__ uint32_t smw[];
    __shared__ float sB1[HID_], sW2[HID_], sred[8];
    const int m = blockIdx.z;
    const int row0 = blockIdx.x * 128;
    const int tid = threadIdx.x;
    const int lane = tid & 31, warp = tid >> 5;
    const int g = lane >> 2, tg = lane & 3;
    const int warpM0 = (warp & 3) * 32;
    const int warpN0 = (warp >> 2) * 64;

    if (tid < HID_) { sB1[tid] = b1[tid]; sW2[tid] = W2[tid]; }

    const int r = tid >> 1, half = tid & 1;
    const int db = r * 33 + half * 16;             // 132 words = 33 uint4 per row
    const int gr = row0 + r;
    {
        uint4* dA = (uint4*)smw;
        uint4* dB1 = (uint4*)(smw + S_S1);
        if (gr < NN) {
            const uint4* sh = (const uint4*)g_zhi + ((size_t)m * NN + gr) * 32 + half * 16;
#pragma unroll
            for (int j = 0; j < 16; j++) dA[db + j] = sh[j];
        } else {
            uint4 zz = make_uint4(0u, 0u, 0u, 0u);
#pragma unroll
            for (int j = 0; j < 16; j++) dA[db + j] = zz;
        }
        const uint4* w1h = (const uint4*)g_W1hi + (size_t)r * 32 + half * 16;
#pragma unroll
        for (int j = 0; j < 16; j++) dB1[db + j] = w1h[j];
    }
    __syncthreads();

    float acc[2][8][4];
#pragma unroll
    for (int i = 0; i < 2; i++)
#pragma unroll
        for (int j = 0; j < 8; j++)
#pragma unroll
            for (int q = 0; q < 4; q++) acc[i][j][q] = 0.0f;

    gemm_pass<S_PITCH, 16>(smw, smw + S_S1, acc, warpM0, warpN0, g, tg);   // A * W1

    // ---- fused epilogue: p = sum tanh(acc + b1) * W2 over this thread's elements ----
    float p = 0.f;
#pragma unroll
    for (int mf = 0; mf < 2; mf++) {
        const int grow = row0 + warpM0 + mf * 16 + g;
        const bool v0 = grow < NN, v1 = grow + 8 < NN;
#pragma unroll
        for (int nf = 0; nf < 8; nf++) {
            const int col = warpN0 + nf * 8 + tg * 2;
            if (v0) {
                p = fmaf(tanhf(acc[mf][nf][0] + sB1[col]),     sW2[col],     p);
                p = fmaf(tanhf(acc[mf][nf][1] + sB1[col + 1]), sW2[col + 1], p);
            }
            if (v1) {
                p = fmaf(tanhf(acc[mf][nf][2] + sB1[col]),     sW2[col],     p);
                p = fmaf(tanhf(acc[mf][nf][3] + sB1[col + 1]), sW2[col + 1], p);
            }
        }
    }
#pragma unroll
    for (int o = 16; o; o >>= 1) p += __shfl_xor_sync(0xffffffffu, p, o);
    if (lane == 0) sred[warp] = p;
    __syncthreads();
    if (tid == 0) {
        float t = 0.f;
#pragma unroll
        for (int w = 0; w < 8; w++) t += sred[w];
        atomicAdd(&g_wsum[m], t);
    }
}

// ================= K7: combine (beta computed per block) =================
__global__ void k_comb(float* __restrict__ out) {
    __shared__ float sb[3];
    if (threadIdx.x == 0) {
        float w0 = g_wsum[0] / (float)NN;
        float w1 = g_wsum[1] / (float)NN;
        float w2 = g_wsum[2] / (float)NN;
        float mx = fmaxf(w0, fmaxf(w1, w2));
        float e0 = __expf(w0 - mx), e1 = __expf(w1 - mx), e2 = __expf(w2 - mx);
        float s = e0 + e1 + e2;
        sb[0] = e0 / s; sb[1] = e1 / s; sb[2] = e2 / s;
    }
    __syncthreads();
    int i = blockIdx.x * blockDim.x + threadIdx.x;
    const int TOT = NN * HD_ / 4;
    if (i >= TOT) return;
    float b0 = sb[0], b1 = sb[1], b2 = sb[2];
    const float4* z = (const float4*)g_z;
    const size_t S = (size_t)NN * (HD_ / 4);
    float4 a = z[i], b = z[S + i], c = z[2 * S + i];
    ((float4*)out)[i] = make_float4(b0 * a.x + b1 * b.x + b2 * c.x,
                                    b0 * a.y + b1 * b.y + b2 * c.y,
                                    b0 * a.z + b1 * b.z + b2 * c.z,
                                    b0 * a.w + b1 * b.w + b2 * c.w);
}

// ================= launcher =================
extern "C" void kernel_launch(void* const* d_in, const int* in_sizes, int n_in,
                              void* d_out, int out_size) {
    const float* h    = (const float*)d_in[0];
    const int*   src  = (const int*)d_in[1];
    const int*   dst  = (const int*)d_in[2];
    const float* W    = (const float*)d_in[3];
    const float* al   = (const float*)d_in[4];
    const float* ar   = (const float*)d_in[5];
    const float* bias = (const float*)d_in[6];
    const float* sW1  = (const float*)d_in[7];
    const float* sb1  = (const float*)d_in[8];
    const float* sW2  = (const float*)d_in[9];
    float* out = (float*)d_out;

    cudaFuncSetAttribute(k_mma_feat, cudaFuncAttributeMaxDynamicSharedMemorySize, F_SMEM_BYTES);
    cudaFuncSetAttribute(k_mma_sem, cudaFuncAttributeMaxDynamicSharedMemorySize, S_SMEM_BYTES);

    const int NTILES = (NN + 127) / 128;   // 157

    k_prep<<<(NN * IN_ + 255) / 256, 256>>>(h, W, sW1);
    k_hist<<<(MM * EE + 255) / 256, 256>>>(dst);

    dim3 gf(NTILES, 2, MM);
    k_mma_feat<<<gf, 256, F_SMEM_BYTES>>>(al, ar);

    k_scan<<<MM, 512>>>();
    k_scatter<<<(MM * EE + 255) / 256, 256>>>(src, dst);
    k_agg<<<(MM * NN * 32 + 255) / 256, 256>>>(bias);

    dim3 gs(NTILES, 1, MM);
    k_mma_sem<<<gs, 256, S_SMEM_BYTES>>>(sb1, sW2);
    k_comb<<<(NN * HD_ / 4 + 255) / 256, 256>>>(out);
}

// round 8
// speedup vs baseline: 1.8165x; 1.0933x over previous
#include <cuda_runtime.h>
#include <cuda_bf16.h>
#include <cuda_fp16.h>
#include <cstdint>

#define NN   20000
#define EE   320000
#define MM   3
#define IN_  128
#define HH   4
#define DD   64
#define HD_  256
#define HID_ 128

#define SCB  2048
#define NSB  ((NN + SCB - 1) / SCB)   // 10

// ================= scratch (static device globals; no allocation) =================
__device__ __align__(16) __half g_feat16[(size_t)MM * NN * HD_];
__device__ __align__(16) float g_z[(size_t)MM * NN * HD_];
__device__ __align__(16) __nv_bfloat16 g_zhi[(size_t)MM * NN * HD_];
__device__ __align__(16) __nv_bfloat16 g_hhi[(size_t)NN * IN_];
__device__ __align__(16) __nv_bfloat16 g_hlo[(size_t)NN * IN_];
__device__ __align__(16) __nv_bfloat16 g_Whi[(size_t)MM * HD_ * IN_];   // [m][n][k]  (W^T, k-contig)
__device__ __align__(16) __nv_bfloat16 g_Wlo[(size_t)MM * HD_ * IN_];
__device__ __align__(16) __nv_bfloat16 g_W1hi[(size_t)HID_ * HD_];      // [n][k]
__device__ __align__(16) float g_el[MM * NN * HH];
__device__ __align__(16) float g_er[MM * NN * HH];
__device__ int   g_cnt[MM * NN];
__device__ int   g_off[MM * (NN + 1)];
__device__ int   g_cur[MM * NN];
__device__ int   g_esrc[MM * EE];
__device__ int   g_bsum[MM * NSB];
__device__ float g_wsum[MM];

// ================= HMMA helper (plain sm_80+ mma.sync — no 'a' features) =================
#define MMA_BF16(c, a0, a1, a2, a3, b0, b1) \
    asm volatile("mma.sync.aligned.m16n8k16.row.col.f32.bf16.bf16.f32 " \
                 "{%0,%1,%2,%3}, {%4,%5,%6,%7}, {%8,%9}, {%0,%1,%2,%3};" \
                 : "+f"((c)[0]), "+f"((c)[1]), "+f"((c)[2]), "+f"((c)[3]) \
                 : "r"(a0), "r"(a1), "r"(a2), "r"(a3), "r"(b0), "r"(b1))

// One K-sweep of a 128x128 CTA tile: 8 warps as 4x2 (warp tile 32x64).
// A in smem [128 rows][PITCHW words] k-contig; B in smem [128 n][PITCHW words] k-contig.
// PITCHW % 32 == 4 -> fragment loads are bank-conflict-free.
template <int PITCHW, int NK>
__device__ __forceinline__ void gemm_pass(const uint32_t* __restrict__ A,
                                          const uint32_t* __restrict__ B,
                                          float acc[2][8][4], int warpM0, int warpN0,
                                          int g, int tg) {
#pragma unroll
    for (int kk = 0; kk < NK; kk++) {
        const int kw = kk * 8 + tg;
        uint32_t a[2][4];
#pragma unroll
        for (int mf = 0; mf < 2; mf++) {
            const int rb = (warpM0 + mf * 16 + g) * PITCHW + kw;
            a[mf][0] = A[rb];
            a[mf][1] = A[rb + 8 * PITCHW];
            a[mf][2] = A[rb + 4];
            a[mf][3] = A[rb + 8 * PITCHW + 4];
        }
#pragma unroll
        for (int nf = 0; nf < 8; nf++) {
            const int nb = (warpN0 + nf * 8 + g) * PITCHW + kw;
            const uint32_t b0 = B[nb];
            const uint32_t b1 = B[nb + 4];
            MMA_BF16(acc[0][nf], a[0][0], a[0][1], a[0][2], a[0][3], b0, b1);
            MMA_BF16(acc[1][nf], a[1][0], a[1][1], a[1][2], a[1][3], b0, b1);
        }
    }
}

// ================= K0: fused prep — zero counters + all fp32->bf16 conversions =========
__global__ void k_prep(const float* __restrict__ h, const float* __restrict__ W,
                       const float* __restrict__ W1) {
    int i = blockIdx.x * blockDim.x + threadIdx.x;
    if (i < NN * IN_) {
        float x = h[i];
        __nv_bfloat16 hi = __float2bfloat16(x);
        g_hhi[i] = hi;
        g_hlo[i] = __float2bfloat16(x - __bfloat162float(hi));
    }
    if (i < MM * IN_ * HD_) {
        int m = i / (IN_ * HD_);
        int r = i - m * (IN_ * HD_);
        int k = r / HD_, n = r - (r / HD_) * HD_;
        float x = W[i];
        __nv_bfloat16 hi = __float2bfloat16(x);
        size_t o = (size_t)m * HD_ * IN_ + (size_t)n * IN_ + k;
        g_Whi[o] = hi;
        g_Wlo[o] = __float2bfloat16(x - __bfloat162float(hi));
    }
    if (i < HD_ * HID_) {
        int k = i / HID_, n = i - (i / HID_) * HID_;
        g_W1hi[(size_t)n * HD_ + k] = __float2bfloat16(W1[i]);
    }
    if (i < MM * NN) g_cnt[i] = 0;
    if (i < MM) g_wsum[i] = 0.0f;
}

// ================= K1: feat = h @ W (HMMA hi/lo x3) + FUSED el/er  grid (157, 2, 3) ====
// smem (words): AHI @0, ALO @8704, BHI @17408, BLO @26112  (pitch 68 words = 136 bf16)
#define F_PITCH 68
#define F_ALO   8704
#define F_BHI   17408
#define F_BLO   26112
#define F_SMEM_BYTES (4 * 128 * F_PITCH * 4)   // 139264

__global__ void __launch_bounds__(256, 1) k_mma_feat(const float* __restrict__ attn_l,
                                                     const float* __restrict__ attn_r) {
    extern __shared__ uint32_t smw[];
    __shared__ float sAL[128], sAR[128];
    const int m = blockIdx.z;
    const int row0 = blockIdx.x * 128;
    const int ncol0 = blockIdx.y * 128;
    const int tid = threadIdx.x;
    const int lane = tid & 31, warp = tid >> 5;
    const int g = lane >> 2, tg = lane & 3;
    const int warpM0 = (warp & 3) * 32;
    const int warpN0 = (warp >> 2) * 64;

    if (tid < 128) {
        sAL[tid] = attn_l[m * HD_ + ncol0 + tid];
        sAR[tid] = attn_r[m * HD_ + ncol0 + tid];
    }

    // ---- load tiles (each thread: one (row, half), 8 uint4 per region) ----
    {
        const int r = tid >> 1, half = tid & 1;
        uint4* dAH = (uint4*)smw;
        uint4* dAL = (uint4*)(smw + F_ALO);
        uint4* dBH = (uint4*)(smw + F_BHI);
        uint4* dBL = (uint4*)(smw + F_BLO);
        const int db = r * 17 + half * 8;          // 68 words = 17 uint4 per row
        const int gr = row0 + r;
        if (gr < NN) {
            const uint4* sh = (const uint4*)g_hhi + (size_t)gr * 16 + half * 8;
            const uint4* sl = (const uint4*)g_hlo + (size_t)gr * 16 + half * 8;
#pragma unroll
            for (int j = 0; j < 8; j++) { dAH[db + j] = sh[j]; dAL[db + j] = sl[j]; }
        } else {
            uint4 zz = make_uint4(0u, 0u, 0u, 0u);
#pragma unroll
            for (int j = 0; j < 8; j++) { dAH[db + j] = zz; dAL[db + j] = zz; }
        }
        const uint4* wh = (const uint4*)g_Whi + ((size_t)m * HD_ + ncol0 + r) * 16 + half * 8;
        const uint4* wl = (const uint4*)g_Wlo + ((size_t)m * HD_ + ncol0 + r) * 16 + half * 8;
#pragma unroll
        for (int j = 0; j < 8; j++) { dBH[db + j] = wh[j]; dBL[db + j] = wl[j]; }
    }
    __syncthreads();

    float acc[2][8][4];
#pragma unroll
    for (int i = 0; i < 2; i++)
#pragma unroll
        for (int j = 0; j < 8; j++)
#pragma unroll
            for (int q = 0; q < 4; q++) acc[i][j][q] = 0.0f;

    gemm_pass<F_PITCH, 8>(smw, smw + F_BHI, acc, warpM0, warpN0, g, tg);          // AH*BH
    gemm_pass<F_PITCH, 8>(smw, smw + F_BLO, acc, warpM0, warpN0, g, tg);          // AH*BL
    gemm_pass<F_PITCH, 8>(smw + F_ALO, smw + F_BHI, acc, warpM0, warpN0, g, tg);  // AL*BH

    // ---- epilogue: store feat (fp16) + fused per-head el/er partial dots ----
    float pl[4] = {0.f, 0.f, 0.f, 0.f};     // rows warpM0+g + {0,8,16,24}
    float pr[4] = {0.f, 0.f, 0.f, 0.f};
#pragma unroll
    for (int mf = 0; mf < 2; mf++) {
        const int grow = row0 + warpM0 + mf * 16 + g;
#pragma unroll
        for (int nf = 0; nf < 8; nf++) {
            const int lc = warpN0 + nf * 8 + tg * 2;
            const int gcol = ncol0 + lc;
            if (grow < NN) {
                __half2 hh;
                hh.x = __float2half_rn(acc[mf][nf][0]);
                hh.y = __float2half_rn(acc[mf][nf][1]);
                *(__half2*)&g_feat16[((size_t)m * NN + grow) * HD_ + gcol] = hh;
            }
            if (grow + 8 < NN) {
                __half2 hh;
                hh.x = __float2half_rn(acc[mf][nf][2]);
                hh.y = __float2half_rn(acc[mf][nf][3]);
                *(__half2*)&g_feat16[((size_t)m * NN + grow + 8) * HD_ + gcol] = hh;
            }
            pl[mf * 2]     += acc[mf][nf][0] * sAL[lc] + acc[mf][nf][1] * sAL[lc + 1];
            pl[mf * 2 + 1] += acc[mf][nf][2] * sAL[lc] + acc[mf][nf][3] * sAL[lc + 1];
            pr[mf * 2]     += acc[mf][nf][0] * sAR[lc] + acc[mf][nf][1] * sAR[lc + 1];
            pr[mf * 2 + 1] += acc[mf][nf][2] * sAR[lc] + acc[mf][nf][3] * sAR[lc + 1];
        }
    }
#pragma unroll
    for (int s = 0; s < 4; s++) {
        pl[s] += __shfl_xor_sync(0xffffffffu, pl[s], 1);
        pl[s] += __shfl_xor_sync(0xffffffffu, pl[s], 2);
        pr[s] += __shfl_xor_sync(0xffffffffu, pr[s], 1);
        pr[s] += __shfl_xor_sync(0xffffffffu, pr[s], 2);
    }
    if (tg == 0) {
        const int head = 2 * blockIdx.y + (warp >> 2);
#pragma unroll
        for (int s = 0; s < 4; s++) {
            const int grow = row0 + warpM0 + g + s * 8;
            if (grow < NN) {
                g_el[(size_t)(m * NN + grow) * HH + head] = pl[s];
                g_er[(size_t)(m * NN + grow) * HH + head] = pr[s];
            }
        }
    }
}

// ================= K2-K5: CSR build (wide two-phase scan) =================
__global__ void k_hist(const int* __restrict__ dst) {
    int i = blockIdx.x * blockDim.x + threadIdx.x;
    if (i >= MM * EE) return;
    int m = i / EE;
    atomicAdd(&g_cnt[m * NN + dst[i]], 1);
}

// phase 1: block-local exclusive scan of 2048 counts; write local prefixes + block sum
__global__ void k_scan1() {
    const int m = blockIdx.y, b = blockIdx.x, t = threadIdx.x;
    __shared__ int sc[256];
    const int base = b * SCB + t * 8;
    int c[8];
    int s = 0;
#pragma unroll
    for (int i = 0; i < 8; i++) {
        int idx = base + i;
        c[i] = (idx < NN) ? g_cnt[m * NN + idx] : 0;
        s += c[i];
    }
    sc[t] = s;
    __syncthreads();
    for (int off = 1; off < 256; off <<= 1) {
        int v = (t >= off) ? sc[t - off] : 0;
        __syncthreads();
        sc[t] += v;
        __syncthreads();
    }
    int ex = t ? sc[t - 1] : 0;
#pragma unroll
    for (int i = 0; i < 8; i++) {
        int idx = base + i;
        if (idx < NN) { g_off[m * (NN + 1) + idx] = ex; ex += c[i]; }
    }
    if (t == 255) g_bsum[m * NSB + b] = sc[255];
}

// phase 2: add block base (thread 0 re-sums <=9 bsums), fill g_off/g_cur (+ total)
__global__ void k_scan3() {
    const int m = blockIdx.y, b = blockIdx.x, t = threadIdx.x;
    __shared__ int sbase;
    if (t == 0) {
        int acc = 0;
        for (int i = 0; i < b; i++) acc += g_bsum[m * NSB + i];
        sbase = acc;
        if (b == NSB - 1) {
            int tot = acc;
            for (int i = b; i < NSB; i++) tot += g_bsum[m * NSB + i];
            g_off[m * (NN + 1) + NN] = tot;
        }
    }
    __syncthreads();
    const int base = b * SCB + t * 8;
    const int sb = sbase;
#pragma unroll
    for (int i = 0; i < 8; i++) {
        int idx = base + i;
        if (idx < NN) {
            int v = g_off[m * (NN + 1) + idx] + sb;
            g_off[m * (NN + 1) + idx] = v;
            g_cur[m * NN + idx] = v;
        }
    }
}

__global__ void k_scatter(const int* __restrict__ src, const int* __restrict__ dst) {
    int i = blockIdx.x * blockDim.x + threadIdx.x;
    if (i >= MM * EE) return;
    int m = i / EE;
    int p = atomicAdd(&g_cur[m * NN + dst[i]], 1);
    g_esrc[(size_t)m * EE + p] = src[i];
}

// ================= K6: edge softmax + aggregation (fp16 gather); writes z ==============
__global__ void k_agg(const float* __restrict__ bias) {
    int gw = (blockIdx.x * blockDim.x + threadIdx.x) >> 5;
    int lane = threadIdx.x & 31;
    if (gw >= MM * NN) return;
    int m = gw / NN, n = gw - m * NN;
    int start = g_off[m * (NN + 1) + n];
    int end   = g_off[m * (NN + 1) + n + 1];
    const size_t mbase = (size_t)m * NN;
    float4 er4 = *(const float4*)&g_er[(mbase + n) * HH];
    const int* esrc = &g_esrc[(size_t)m * EE];

    // pass A: per-head denominators
    float s0 = 0.f, s1 = 0.f, s2 = 0.f, s3 = 0.f;
    for (int e = start + lane; e < end; e += 32) {
        int s = esrc[e];
        float4 el4 = *(const float4*)&g_el[(mbase + s) * HH];
        float e0 = el4.x + er4.x; e0 = e0 > 0.f ? e0 : 0.2f * e0; s0 += __expf(e0);
        float e1 = el4.y + er4.y; e1 = e1 > 0.f ? e1 : 0.2f * e1; s1 += __expf(e1);
        float e2 = el4.z + er4.z; e2 = e2 > 0.f ? e2 : 0.2f * e2; s2 += __expf(e2);
        float e3 = el4.w + er4.w; e3 = e3 > 0.f ? e3 : 0.2f * e3; s3 += __expf(e3);
    }
#pragma unroll
    for (int o = 16; o; o >>= 1) {
        s0 += __shfl_xor_sync(0xffffffffu, s0, o);
        s1 += __shfl_xor_sync(0xffffffffu, s1, o);
        s2 += __shfl_xor_sync(0xffffffffu, s2, o);
        s3 += __shfl_xor_sync(0xffffffffu, s3, o);
    }
    float rd0 = 1.f / fmaxf(s0, 1e-9f);
    float rd1 = 1.f / fmaxf(s1, 1e-9f);
    float rd2 = 1.f / fmaxf(s2, 1e-9f);
    float rd3 = 1.f / fmaxf(s3, 1e-9f);

    // pass B: lane owns 8 contiguous channels [8*lane .. 8*lane+7] (head = lane>>3)
    float acc[8];
#pragma unroll
    for (int k = 0; k < 8; k++) acc[k] = 0.f;
    const uint4* fv = (const uint4*)g_feat16;   // 8 halves per uint4

    for (int j = start; j < end; j += 32) {
        int myE = j + lane;
        int cnt = min(32, end - j);
        int smy = (myE < end) ? esrc[myE] : 0;
        float4 el4 = *(const float4*)&g_el[(mbase + smy) * HH];
        float e0 = el4.x + er4.x; e0 = e0 > 0.f ? e0 : 0.2f * e0;
        float e1 = el4.y + er4.y; e1 = e1 > 0.f ? e1 : 0.2f * e1;
        float e2 = el4.z + er4.z; e2 = e2 > 0.f ? e2 : 0.2f * e2;
        float e3 = el4.w + er4.w; e3 = e3 > 0.f ? e3 : 0.2f * e3;
        float w0my = __expf(e0) * rd0;
        float w1my = __expf(e1) * rd1;
        float w2my = __expf(e2) * rd2;
        float w3my = __expf(e3) * rd3;
        for (int t = 0; t < cnt; t++) {
            int s = __shfl_sync(0xffffffffu, smy, t);
            float b0 = __shfl_sync(0xffffffffu, w0my, t);
            float b1 = __shfl_sync(0xffffffffu, w1my, t);
            float b2 = __shfl_sync(0xffffffffu, w2my, t);
            float b3 = __shfl_sync(0xffffffffu, w3my, t);
            float wlo = (lane & 8) ? b1 : b0;
            float whi = (lane & 8) ? b3 : b2;
            float w = (lane & 16) ? whi : wlo;
            uint4 pk = fv[(mbase + s) * (HD_ / 8) + lane];
            const __half2* hp = (const __half2*)&pk;
            float2 p0 = __half22float2(hp[0]);
            float2 p1 = __half22float2(hp[1]);
            float2 p2 = __half22float2(hp[2]);
            float2 p3 = __half22float2(hp[3]);
            acc[0] = fmaf(w, p0.x, acc[0]); acc[1] = fmaf(w, p0.y, acc[1]);
            acc[2] = fmaf(w, p1.x, acc[2]); acc[3] = fmaf(w, p1.y, acc[3]);
            acc[4] = fmaf(w, p2.x, acc[4]); acc[5] = fmaf(w, p2.y, acc[5]);
            acc[6] = fmaf(w, p3.x, acc[6]); acc[7] = fmaf(w, p3.y, acc[7]);
        }
    }
    const int c0 = lane * 8;
    const float* bv = &bias[m * HD_ + c0];
    float o[8];
#pragma unroll
    for (int k = 0; k < 8; k++) o[k] = acc[k] + bv[k];
    size_t zb = (mbase + n) * HD_ + c0;
    *(float4*)&g_z[zb]     = make_float4(o[0], o[1], o[2], o[3]);
    *(float4*)&g_z[zb + 4] = make_float4(o[4], o[5], o[6], o[7]);
    __nv_bfloat162 zh[4];
#pragma unroll
    for (int k = 0; k < 4; k++) {
        zh[k].x = __float2bfloat16(o[2 * k]);
        zh[k].y = __float2bfloat16(o[2 * k + 1]);
    }
    *(uint4*)&g_zhi[zb] = *(uint4*)zh;
}

// ================= K7: semantic GEMM (HMMA, single bf16 pass) + fused epilogue =========
// smem regions of 128 rows x 132 words: S0 @0 : A(zhi)   S1 @16896 : W1hi
#define S_PITCH 132
#define S_S1    16896
#define S_SMEM_BYTES (2 * 128 * S_PITCH * 4)   // 135168

__global__ void __launch_bounds__(256, 1) k_mma_sem(const float* __restrict__ b1,
                                                    const float* __restrict__ W2) {
    extern __shared__ uint32_t smw[];
    __shared__ float sB1[HID_], sW2[HID_], sred[8];
    const int m = blockIdx.z;
    const int row0 = blockIdx.x * 128;
    const int tid = threadIdx.x;
    const int lane = tid & 31, warp = tid >> 5;
    const int g = lane >> 2, tg = lane & 3;
    const int warpM0 = (warp & 3) * 32;
    const int warpN0 = (warp >> 2) * 64;

    if (tid < HID_) { sB1[tid] = b1[tid]; sW2[tid] = W2[tid]; }

    const int r = tid >> 1, half = tid & 1;
    const int db = r * 33 + half * 16;             // 132 words = 33 uint4 per row
    const int gr = row0 + r;
    {
        uint4* dA = (uint4*)smw;
        uint4* dB1 = (uint4*)(smw + S_S1);
        if (gr < NN) {
            const uint4* sh = (const uint4*)g_zhi + ((size_t)m * NN + gr) * 32 + half * 16;
#pragma unroll
            for (int j = 0; j < 16; j++) dA[db + j] = sh[j];
        } else {
            uint4 zz = make_uint4(0u, 0u, 0u, 0u);
#pragma unroll
            for (int j = 0; j < 16; j++) dA[db + j] = zz;
        }
        const uint4* w1h = (const uint4*)g_W1hi + (size_t)r * 32 + half * 16;
#pragma unroll
        for (int j = 0; j < 16; j++) dB1[db + j] = w1h[j];
    }
    __syncthreads();

    float acc[2][8][4];
#pragma unroll
    for (int i = 0; i < 2; i++)
#pragma unroll
        for (int j = 0; j < 8; j++)
#pragma unroll
            for (int q = 0; q < 4; q++) acc[i][j][q] = 0.0f;

    gemm_pass<S_PITCH, 16>(smw, smw + S_S1, acc, warpM0, warpN0, g, tg);   // A * W1

    // ---- fused epilogue: p = sum tanh(acc + b1) * W2 over this thread's elements ----
    float p = 0.f;
#pragma unroll
    for (int mf = 0; mf < 2; mf++) {
        const int grow = row0 + warpM0 + mf * 16 + g;
        const bool v0 = grow < NN, v1 = grow + 8 < NN;
#pragma unroll
        for (int nf = 0; nf < 8; nf++) {
            const int col = warpN0 + nf * 8 + tg * 2;
            if (v0) {
                p = fmaf(tanhf(acc[mf][nf][0] + sB1[col]),     sW2[col],     p);
                p = fmaf(tanhf(acc[mf][nf][1] + sB1[col + 1]), sW2[col + 1], p);
            }
            if (v1) {
                p = fmaf(tanhf(acc[mf][nf][2] + sB1[col]),     sW2[col],     p);
                p = fmaf(tanhf(acc[mf][nf][3] + sB1[col + 1]), sW2[col + 1], p);
            }
        }
    }
#pragma unroll
    for (int o = 16; o; o >>= 1) p += __shfl_xor_sync(0xffffffffu, p, o);
    if (lane == 0) sred[warp] = p;
    __syncthreads();
    if (tid == 0) {
        float t = 0.f;
#pragma unroll
        for (int w = 0; w < 8; w++) t += sred[w];
        atomicAdd(&g_wsum[m], t);
    }
}

// ================= K8: combine (beta computed per block) =================
__global__ void k_comb(float* __restrict__ out) {
    __shared__ float sb[3];
    if (threadIdx.x == 0) {
        float w0 = g_wsum[0] / (float)NN;
        float w1 = g_wsum[1] / (float)NN;
        float w2 = g_wsum[2] / (float)NN;
        float mx = fmaxf(w0, fmaxf(w1, w2));
        float e0 = __expf(w0 - mx), e1 = __expf(w1 - mx), e2 = __expf(w2 - mx);
        float s = e0 + e1 + e2;
        sb[0] = e0 / s; sb[1] = e1 / s; sb[2] = e2 / s;
    }
    __syncthreads();
    int i = blockIdx.x * blockDim.x + threadIdx.x;
    const int TOT = NN * HD_ / 4;
    if (i >= TOT) return;
    float b0 = sb[0], b1 = sb[1], b2 = sb[2];
    const float4* z = (const float4*)g_z;
    const size_t S = (size_t)NN * (HD_ / 4);
    float4 a = z[i], b = z[S + i], c = z[2 * S + i];
    ((float4*)out)[i] = make_float4(b0 * a.x + b1 * b.x + b2 * c.x,
                                    b0 * a.y + b1 * b.y + b2 * c.y,
                                    b0 * a.z + b1 * b.z + b2 * c.z,
                                    b0 * a.w + b1 * b.w + b2 * c.w);
}

// ================= launcher =================
extern "C" void kernel_launch(void* const* d_in, const int* in_sizes, int n_in,
                              void* d_out, int out_size) {
    const float* h    = (const float*)d_in[0];
    const int*   src  = (const int*)d_in[1];
    const int*   dst  = (const int*)d_in[2];
    const float* W    = (const float*)d_in[3];
    const float* al   = (const float*)d_in[4];
    const float* ar   = (const float*)d_in[5];
    const float* bias = (const float*)d_in[6];
    const float* sW1  = (const float*)d_in[7];
    const float* sb1  = (const float*)d_in[8];
    const float* sW2  = (const float*)d_in[9];
    float* out = (float*)d_out;

    cudaFuncSetAttribute(k_mma_feat, cudaFuncAttributeMaxDynamicSharedMemorySize, F_SMEM_BYTES);
    cudaFuncSetAttribute(k_mma_sem, cudaFuncAttributeMaxDynamicSharedMemorySize, S_SMEM_BYTES);

    const int NTILES = (NN + 127) / 128;   // 157

    k_prep<<<(NN * IN_ + 255) / 256, 256>>>(h, W, sW1);
    k_hist<<<(MM * EE + 255) / 256, 256>>>(dst);

    dim3 gf(NTILES, 2, MM);
    k_mma_feat<<<gf, 256, F_SMEM_BYTES>>>(al, ar);

    dim3 gsc(NSB, MM);
    k_scan1<<<gsc, 256>>>();
    k_scan3<<<gsc, 256>>>();
    k_scatter<<<(MM * EE + 255) / 256, 256>>>(src, dst);
    k_agg<<<(MM * NN * 32 + 255) / 256, 256>>>(bias);

    dim3 gs(NTILES, 1, MM);
    k_mma_sem<<<gs, 256, S_SMEM_BYTES>>>(sb1, sW2);
    k_comb<<<(NN * HD_ / 4 + 255) / 256, 256>>>(out);
}

// round 9
// speedup vs baseline: 2.0244x; 1.1144x over previous
#include <cuda_runtime.h>
#include <cuda_bf16.h>
#include <cuda_fp16.h>
#include <cstdint>

#define NN   20000
#define EE   320000
#define MM   3
#define IN_  128
#define HH   4
#define DD   64
#define HD_  256
#define HID_ 128

#define SCB  2048
#define NSB  ((NN + SCB - 1) / SCB)   // 10

// ================= scratch (static device globals; no allocation) =================
__device__ __align__(16) __half g_feat16[(size_t)MM * NN * HD_];
__device__ __align__(16) float g_z[(size_t)MM * NN * HD_];
__device__ __align__(16) __nv_bfloat16 g_zhi[(size_t)MM * NN * HD_];
__device__ __align__(16) __nv_bfloat16 g_hhi[(size_t)NN * IN_];
__device__ __align__(16) __nv_bfloat16 g_hlo[(size_t)NN * IN_];
__device__ __align__(16) __nv_bfloat16 g_Whi[(size_t)MM * HD_ * IN_];   // [m][n][k]  (W^T, k-contig)
__device__ __align__(16) __nv_bfloat16 g_Wlo[(size_t)MM * HD_ * IN_];
__device__ __align__(16) __nv_bfloat16 g_W1hi[(size_t)HID_ * HD_];      // [n][k]
__device__ __align__(16) float g_el[MM * NN * HH];
__device__ __align__(16) float g_er[MM * NN * HH];
__device__ int   g_cnt[MM * NN];
__device__ int   g_off[MM * (NN + 1)];
__device__ int   g_cur[MM * NN];
__device__ int   g_esrc[MM * EE];
__device__ int   g_bsum[MM * NSB];
__device__ float g_wsum[MM];

// ================= HMMA helper (plain sm_80+ mma.sync — no 'a' features) =================
#define MMA_BF16(c, a0, a1, a2, a3, b0, b1) \
    asm volatile("mma.sync.aligned.m16n8k16.row.col.f32.bf16.bf16.f32 " \
                 "{%0,%1,%2,%3}, {%4,%5,%6,%7}, {%8,%9}, {%0,%1,%2,%3};" \
                 : "+f"((c)[0]), "+f"((c)[1]), "+f"((c)[2]), "+f"((c)[3]) \
                 : "r"(a0), "r"(a1), "r"(a2), "r"(a3), "r"(b0), "r"(b1))

template <int PITCHW, int NK>
__device__ __forceinline__ void gemm_pass(const uint32_t* __restrict__ A,
                                          const uint32_t* __restrict__ B,
                                          float acc[2][8][4], int warpM0, int warpN0,
                                          int g, int tg) {
#pragma unroll
    for (int kk = 0; kk < NK; kk++) {
        const int kw = kk * 8 + tg;
        uint32_t a[2][4];
#pragma unroll
        for (int mf = 0; mf < 2; mf++) {
            const int rb = (warpM0 + mf * 16 + g) * PITCHW + kw;
            a[mf][0] = A[rb];
            a[mf][1] = A[rb + 8 * PITCHW];
            a[mf][2] = A[rb + 4];
            a[mf][3] = A[rb + 8 * PITCHW + 4];
        }
#pragma unroll
        for (int nf = 0; nf < 8; nf++) {
            const int nb = (warpN0 + nf * 8 + g) * PITCHW + kw;
            const uint32_t b0 = B[nb];
            const uint32_t b1 = B[nb + 4];
            MMA_BF16(acc[0][nf], a[0][0], a[0][1], a[0][2], a[0][3], b0, b1);
            MMA_BF16(acc[1][nf], a[1][0], a[1][1], a[1][2], a[1][3], b0, b1);
        }
    }
}

// ================= K0: fused prep — zero counters + all fp32->bf16 conversions =========
__global__ void k_prep(const float* __restrict__ h, const float* __restrict__ W,
                       const float* __restrict__ W1) {
    int i = blockIdx.x * blockDim.x + threadIdx.x;
    if (i < NN * IN_) {
        float x = h[i];
        __nv_bfloat16 hi = __float2bfloat16(x);
        g_hhi[i] = hi;
        g_hlo[i] = __float2bfloat16(x - __bfloat162float(hi));
    }
    if (i < MM * IN_ * HD_) {
        int m = i / (IN_ * HD_);
        int r = i - m * (IN_ * HD_);
        int k = r / HD_, n = r - (r / HD_) * HD_;
        float x = W[i];
        __nv_bfloat16 hi = __float2bfloat16(x);
        size_t o = (size_t)m * HD_ * IN_ + (size_t)n * IN_ + k;
        g_Whi[o] = hi;
        g_Wlo[o] = __float2bfloat16(x - __bfloat162float(hi));
    }
    if (i < HD_ * HID_) {
        int k = i / HID_, n = i - (i / HID_) * HID_;
        g_W1hi[(size_t)n * HD_ + k] = __float2bfloat16(W1[i]);
    }
    if (i < MM * NN) g_cnt[i] = 0;
    if (i < MM) g_wsum[i] = 0.0f;
}

// ================= K1: feat = h @ W (HMMA hi/lo x3) + FUSED el/er  grid (157, 2, 3) ====
#define F_PITCH 68
#define F_ALO   8704
#define F_BHI   17408
#define F_BLO   26112
#define F_SMEM_BYTES (4 * 128 * F_PITCH * 4)   // 139264

__global__ void __launch_bounds__(256, 1) k_mma_feat(const float* __restrict__ attn_l,
                                                     const float* __restrict__ attn_r) {
    extern __shared__ uint32_t smw[];
    __shared__ float sAL[128], sAR[128];
    const int m = blockIdx.z;
    const int row0 = blockIdx.x * 128;
    const int ncol0 = blockIdx.y * 128;
    const int tid = threadIdx.x;
    const int lane = tid & 31, warp = tid >> 5;
    const int g = lane >> 2, tg = lane & 3;
    const int warpM0 = (warp & 3) * 32;
    const int warpN0 = (warp >> 2) * 64;

    if (tid < 128) {
        sAL[tid] = attn_l[m * HD_ + ncol0 + tid];
        sAR[tid] = attn_r[m * HD_ + ncol0 + tid];
    }

    {
        const int r = tid >> 1, half = tid & 1;
        uint4* dAH = (uint4*)smw;
        uint4* dAL = (uint4*)(smw + F_ALO);
        uint4* dBH = (uint4*)(smw + F_BHI);
        uint4* dBL = (uint4*)(smw + F_BLO);
        const int db = r * 17 + half * 8;
        const int gr = row0 + r;
        if (gr < NN) {
            const uint4* sh = (const uint4*)g_hhi + (size_t)gr * 16 + half * 8;
            const uint4* sl = (const uint4*)g_hlo + (size_t)gr * 16 + half * 8;
#pragma unroll
            for (int j = 0; j < 8; j++) { dAH[db + j] = sh[j]; dAL[db + j] = sl[j]; }
        } else {
            uint4 zz = make_uint4(0u, 0u, 0u, 0u);
#pragma unroll
            for (int j = 0; j < 8; j++) { dAH[db + j] = zz; dAL[db + j] = zz; }
        }
        const uint4* wh = (const uint4*)g_Whi + ((size_t)m * HD_ + ncol0 + r) * 16 + half * 8;
        const uint4* wl = (const uint4*)g_Wlo + ((size_t)m * HD_ + ncol0 + r) * 16 + half * 8;
#pragma unroll
        for (int j = 0; j < 8; j++) { dBH[db + j] = wh[j]; dBL[db + j] = wl[j]; }
    }
    __syncthreads();

    float acc[2][8][4];
#pragma unroll
    for (int i = 0; i < 2; i++)
#pragma unroll
        for (int j = 0; j < 8; j++)
#pragma unroll
            for (int q = 0; q < 4; q++) acc[i][j][q] = 0.0f;

    gemm_pass<F_PITCH, 8>(smw, smw + F_BHI, acc, warpM0, warpN0, g, tg);          // AH*BH
    gemm_pass<F_PITCH, 8>(smw, smw + F_BLO, acc, warpM0, warpN0, g, tg);          // AH*BL
    gemm_pass<F_PITCH, 8>(smw + F_ALO, smw + F_BHI, acc, warpM0, warpN0, g, tg);  // AL*BH

    float pl[4] = {0.f, 0.f, 0.f, 0.f};
    float pr[4] = {0.f, 0.f, 0.f, 0.f};
#pragma unroll
    for (int mf = 0; mf < 2; mf++) {
        const int grow = row0 + warpM0 + mf * 16 + g;
#pragma unroll
        for (int nf = 0; nf < 8; nf++) {
            const int lc = warpN0 + nf * 8 + tg * 2;
            const int gcol = ncol0 + lc;
            if (grow < NN) {
                __half2 hh;
                hh.x = __float2half_rn(acc[mf][nf][0]);
                hh.y = __float2half_rn(acc[mf][nf][1]);
                *(__half2*)&g_feat16[((size_t)m * NN + grow) * HD_ + gcol] = hh;
            }
            if (grow + 8 < NN) {
                __half2 hh;
                hh.x = __float2half_rn(acc[mf][nf][2]);
                hh.y = __float2half_rn(acc[mf][nf][3]);
                *(__half2*)&g_feat16[((size_t)m * NN + grow + 8) * HD_ + gcol] = hh;
            }
            pl[mf * 2]     += acc[mf][nf][0] * sAL[lc] + acc[mf][nf][1] * sAL[lc + 1];
            pl[mf * 2 + 1] += acc[mf][nf][2] * sAL[lc] + acc[mf][nf][3] * sAL[lc + 1];
            pr[mf * 2]     += acc[mf][nf][0] * sAR[lc] + acc[mf][nf][1] * sAR[lc + 1];
            pr[mf * 2 + 1] += acc[mf][nf][2] * sAR[lc] + acc[mf][nf][3] * sAR[lc + 1];
        }
    }
#pragma unroll
    for (int s = 0; s < 4; s++) {
        pl[s] += __shfl_xor_sync(0xffffffffu, pl[s], 1);
        pl[s] += __shfl_xor_sync(0xffffffffu, pl[s], 2);
        pr[s] += __shfl_xor_sync(0xffffffffu, pr[s], 1);
        pr[s] += __shfl_xor_sync(0xffffffffu, pr[s], 2);
    }
    if (tg == 0) {
        const int head = 2 * blockIdx.y + (warp >> 2);
#pragma unroll
        for (int s = 0; s < 4; s++) {
            const int grow = row0 + warpM0 + g + s * 8;
            if (grow < NN) {
                g_el[(size_t)(m * NN + grow) * HH + head] = pl[s];
                g_er[(size_t)(m * NN + grow) * HH + head] = pr[s];
            }
        }
    }
}

// ================= K2-K5: CSR build (wide two-phase scan) =================
__global__ void k_hist(const int* __restrict__ dst) {
    int i = blockIdx.x * blockDim.x + threadIdx.x;
    if (i >= MM * EE) return;
    int m = i / EE;
    atomicAdd(&g_cnt[m * NN + dst[i]], 1);
}

__global__ void k_scan1() {
    const int m = blockIdx.y, b = blockIdx.x, t = threadIdx.x;
    __shared__ int sc[256];
    const int base = b * SCB + t * 8;
    int c[8];
    int s = 0;
#pragma unroll
    for (int i = 0; i < 8; i++) {
        int idx = base + i;
        c[i] = (idx < NN) ? g_cnt[m * NN + idx] : 0;
        s += c[i];
    }
    sc[t] = s;
    __syncthreads();
    for (int off = 1; off < 256; off <<= 1) {
        int v = (t >= off) ? sc[t - off] : 0;
        __syncthreads();
        sc[t] += v;
        __syncthreads();
    }
    int ex = t ? sc[t - 1] : 0;
#pragma unroll
    for (int i = 0; i < 8; i++) {
        int idx = base + i;
        if (idx < NN) { g_off[m * (NN + 1) + idx] = ex; ex += c[i]; }
    }
    if (t == 255) g_bsum[m * NSB + b] = sc[255];
}

__global__ void k_scan3() {
    const int m = blockIdx.y, b = blockIdx.x, t = threadIdx.x;
    __shared__ int sbase;
    if (t == 0) {
        int acc = 0;
        for (int i = 0; i < b; i++) acc += g_bsum[m * NSB + i];
        sbase = acc;
        if (b == NSB - 1) {
            int tot = acc;
            for (int i = b; i < NSB; i++) tot += g_bsum[m * NSB + i];
            g_off[m * (NN + 1) + NN] = tot;
        }
    }
    __syncthreads();
    const int base = b * SCB + t * 8;
    const int sb = sbase;
#pragma unroll
    for (int i = 0; i < 8; i++) {
        int idx = base + i;
        if (idx < NN) {
            int v = g_off[m * (NN + 1) + idx] + sb;
            g_off[m * (NN + 1) + idx] = v;
            g_cur[m * NN + idx] = v;
        }
    }
}

__global__ void k_scatter(const int* __restrict__ src, const int* __restrict__ dst) {
    int i = blockIdx.x * blockDim.x + threadIdx.x;
    if (i >= MM * EE) return;
    int m = i / EE;
    int p = atomicAdd(&g_cur[m * NN + dst[i]], 1);
    g_esrc[(size_t)m * EE + p] = src[i];
}

// ================= K6: single-pass edge softmax + aggregation (normalize at end) =======
// Per 32-edge tile: owner lanes compute unnormalized w=exp(leaky(el+er)) for 4 heads,
// stage (src, w0..3) in smem; t-loop unrolled x4 with 4 independent gathers (MLP=4).
__global__ void k_agg(const float* __restrict__ bias) {
    __shared__ float sW[8][32][4];
    __shared__ int   sS[8][32];
    const int wip = threadIdx.x >> 5;
    const int lane = threadIdx.x & 31;
    int gw = (blockIdx.x * blockDim.x + threadIdx.x) >> 5;
    if (gw >= MM * NN) return;
    int m = gw / NN, n = gw - m * NN;
    int start = g_off[m * (NN + 1) + n];
    int end   = g_off[m * (NN + 1) + n + 1];
    const size_t mbase = (size_t)m * NN;
    float4 er4 = *(const float4*)&g_er[(mbase + n) * HH];
    const int* esrc = &g_esrc[(size_t)m * EE];
    const int head = lane >> 3;
    const uint4* fv = (const uint4*)g_feat16;

    float acc[8];
#pragma unroll
    for (int k = 0; k < 8; k++) acc[k] = 0.f;
    float dsum = 0.f;

    for (int j = start; j < end; j += 32) {
        int myE = j + lane;
        int cnt = min(32, end - j);
        int smy = 0;
        float w0 = 0.f, w1 = 0.f, w2 = 0.f, w3 = 0.f;
        if (myE < end) {
            smy = esrc[myE];
            float4 el4 = *(const float4*)&g_el[(mbase + smy) * HH];
            float e0 = el4.x + er4.x; e0 = e0 > 0.f ? e0 : 0.2f * e0; w0 = __expf(e0);
            float e1 = el4.y + er4.y; e1 = e1 > 0.f ? e1 : 0.2f * e1; w1 = __expf(e1);
            float e2 = el4.z + er4.z; e2 = e2 > 0.f ? e2 : 0.2f * e2; w2 = __expf(e2);
            float e3 = el4.w + er4.w; e3 = e3 > 0.f ? e3 : 0.2f * e3; w3 = __expf(e3);
        }
        sS[wip][lane] = smy;
        *(float4*)&sW[wip][lane][0] = make_float4(w0, w1, w2, w3);
        __syncwarp();
        const int cnt4 = (cnt + 3) & ~3;
        for (int t = 0; t < cnt4; t += 4) {
            int s0 = sS[wip][t + 0];
            int s1 = sS[wip][t + 1];
            int s2 = sS[wip][t + 2];
            int s3 = sS[wip][t + 3];
            float wa = sW[wip][t + 0][head];
            float wb = sW[wip][t + 1][head];
            float wc = sW[wip][t + 2][head];
            float wd = sW[wip][t + 3][head];
            uint4 p0 = fv[(mbase + s0) * (HD_ / 8) + lane];
            uint4 p1 = fv[(mbase + s1) * (HD_ / 8) + lane];
            uint4 p2 = fv[(mbase + s2) * (HD_ / 8) + lane];
            uint4 p3 = fv[(mbase + s3) * (HD_ / 8) + lane];
            dsum += (wa + wb) + (wc + wd);
            {
                const __half2* hp = (const __half2*)&p0;
                float2 q0 = __half22float2(hp[0]), q1 = __half22float2(hp[1]);
                float2 q2 = __half22float2(hp[2]), q3 = __half22float2(hp[3]);
                acc[0] = fmaf(wa, q0.x, acc[0]); acc[1] = fmaf(wa, q0.y, acc[1]);
                acc[2] = fmaf(wa, q1.x, acc[2]); acc[3] = fmaf(wa, q1.y, acc[3]);
                acc[4] = fmaf(wa, q2.x, acc[4]); acc[5] = fmaf(wa, q2.y, acc[5]);
                acc[6] = fmaf(wa, q3.x, acc[6]); acc[7] = fmaf(wa, q3.y, acc[7]);
            }
            {
                const __half2* hp = (const __half2*)&p1;
                float2 q0 = __half22float2(hp[0]), q1 = __half22float2(hp[1]);
                float2 q2 = __half22float2(hp[2]), q3 = __half22float2(hp[3]);
                acc[0] = fmaf(wb, q0.x, acc[0]); acc[1] = fmaf(wb, q0.y, acc[1]);
                acc[2] = fmaf(wb, q1.x, acc[2]); acc[3] = fmaf(wb, q1.y, acc[3]);
                acc[4] = fmaf(wb, q2.x, acc[4]); acc[5] = fmaf(wb, q2.y, acc[5]);
                acc[6] = fmaf(wb, q3.x, acc[6]); acc[7] = fmaf(wb, q3.y, acc[7]);
            }
            {
                const __half2* hp = (const __half2*)&p2;
                float2 q0 = __half22float2(hp[0]), q1 = __half22float2(hp[1]);
                float2 q2 = __half22float2(hp[2]), q3 = __half22float2(hp[3]);
                acc[0] = fmaf(wc, q0.x, acc[0]); acc[1] = fmaf(wc, q0.y, acc[1]);
                acc[2] = fmaf(wc, q1.x, acc[2]); acc[3] = fmaf(wc, q1.y, acc[3]);
                acc[4] = fmaf(wc, q2.x, acc[4]); acc[5] = fmaf(wc, q2.y, acc[5]);
                acc[6] = fmaf(wc, q3.x, acc[6]); acc[7] = fmaf(wc, q3.y, acc[7]);
            }
            {
                const __half2* hp = (const __half2*)&p3;
                float2 q0 = __half22float2(hp[0]), q1 = __half22float2(hp[1]);
                float2 q2 = __half22float2(hp[2]), q3 = __half22float2(hp[3]);
                acc[0] = fmaf(wd, q0.x, acc[0]); acc[1] = fmaf(wd, q0.y, acc[1]);
                acc[2] = fmaf(wd, q1.x, acc[2]); acc[3] = fmaf(wd, q1.y, acc[3]);
                acc[4] = fmaf(wd, q2.x, acc[4]); acc[5] = fmaf(wd, q2.y, acc[5]);
                acc[6] = fmaf(wd, q3.x, acc[6]); acc[7] = fmaf(wd, q3.y, acc[7]);
            }
        }
        __syncwarp();
    }

    const float rd = 1.f / fmaxf(dsum, 1e-9f);
    const int c0 = lane * 8;
    const float* bv = &bias[m * HD_ + c0];
    float o[8];
#pragma unroll
    for (int k = 0; k < 8; k++) o[k] = fmaf(acc[k], rd, bv[k]);
    size_t zb = (mbase + n) * HD_ + c0;
    *(float4*)&g_z[zb]     = make_float4(o[0], o[1], o[2], o[3]);
    *(float4*)&g_z[zb + 4] = make_float4(o[4], o[5], o[6], o[7]);
    __nv_bfloat162 zh[4];
#pragma unroll
    for (int k = 0; k < 4; k++) {
        zh[k].x = __float2bfloat16(o[2 * k]);
        zh[k].y = __float2bfloat16(o[2 * k + 1]);
    }
    *(uint4*)&g_zhi[zb] = *(uint4*)zh;
}

// ================= K7: semantic GEMM (HMMA, single bf16 pass) + fused epilogue =========
#define S_PITCH 132
#define S_S1    16896
#define S_SMEM_BYTES (2 * 128 * S_PITCH * 4)   // 135168

__global__ void __launch_bounds__(256, 1) k_mma_sem(const float* __restrict__ b1,
                                                    const float* __restrict__ W2) {
    extern __shared__ uint32_t smw[];
    __shared__ float sB1[HID_], sW2[HID_], sred[8];
    const int m = blockIdx.z;
    const int row0 = blockIdx.x * 128;
    const int tid = threadIdx.x;
    const int lane = tid & 31, warp = tid >> 5;
    const int g = lane >> 2, tg = lane & 3;
    const int warpM0 = (warp & 3) * 32;
    const int warpN0 = (warp >> 2) * 64;

    if (tid < HID_) { sB1[tid] = b1[tid]; sW2[tid] = W2[tid]; }

    const int r = tid >> 1, half = tid & 1;
    const int db = r * 33 + half * 16;
    const int gr = row0 + r;
    {
        uint4* dA = (uint4*)smw;
        uint4* dB1 = (uint4*)(smw + S_S1);
        if (gr < NN) {
            const uint4* sh = (const uint4*)g_zhi + ((size_t)m * NN + gr) * 32 + half * 16;
#pragma unroll
            for (int j = 0; j < 16; j++) dA[db + j] = sh[j];
        } else {
            uint4 zz = make_uint4(0u, 0u, 0u, 0u);
#pragma unroll
            for (int j = 0; j < 16; j++) dA[db + j] = zz;
        }
        const uint4* w1h = (const uint4*)g_W1hi + (size_t)r * 32 + half * 16;
#pragma unroll
        for (int j = 0; j < 16; j++) dB1[db + j] = w1h[j];
    }
    __syncthreads();

    float acc[2][8][4];
#pragma unroll
    for (int i = 0; i < 2; i++)
#pragma unroll
        for (int j = 0; j < 8; j++)
#pragma unroll
            for (int q = 0; q < 4; q++) acc[i][j][q] = 0.0f;

    gemm_pass<S_PITCH, 16>(smw, smw + S_S1, acc, warpM0, warpN0, g, tg);   // A * W1

    float p = 0.f;
#pragma unroll
    for (int mf = 0; mf < 2; mf++) {
        const int grow = row0 + warpM0 + mf * 16 + g;
        const bool v0 = grow < NN, v1 = grow + 8 < NN;
#pragma unroll
        for (int nf = 0; nf < 8; nf++) {
            const int col = warpN0 + nf * 8 + tg * 2;
            if (v0) {
                p = fmaf(tanhf(acc[mf][nf][0] + sB1[col]),     sW2[col],     p);
                p = fmaf(tanhf(acc[mf][nf][1] + sB1[col + 1]), sW2[col + 1], p);
            }
            if (v1) {
                p = fmaf(tanhf(acc[mf][nf][2] + sB1[col]),     sW2[col],     p);
                p = fmaf(tanhf(acc[mf][nf][3] + sB1[col + 1]), sW2[col + 1], p);
            }
        }
    }
#pragma unroll
    for (int o = 16; o; o >>= 1) p += __shfl_xor_sync(0xffffffffu, p, o);
    if (lane == 0) sred[warp] = p;
    __syncthreads();
    if (tid == 0) {
        float t = 0.f;
#pragma unroll
        for (int w = 0; w < 8; w++) t += sred[w];
        atomicAdd(&g_wsum[m], t);
    }
}

// ================= K8: combine (beta computed per block) =================
__global__ void k_comb(float* __restrict__ out) {
    __shared__ float sb[3];
    if (threadIdx.x == 0) {
        float w0 = g_wsum[0] / (float)NN;
        float w1 = g_wsum[1] / (float)NN;
        float w2 = g_wsum[2] / (float)NN;
        float mx = fmaxf(w0, fmaxf(w1, w2));
        float e0 = __expf(w0 - mx), e1 = __expf(w1 - mx), e2 = __expf(w2 - mx);
        float s = e0 + e1 + e2;
        sb[0] = e0 / s; sb[1] = e1 / s; sb[2] = e2 / s;
    }
    __syncthreads();
    int i = blockIdx.x * blockDim.x + threadIdx.x;
    const int TOT = NN * HD_ / 4;
    if (i >= TOT) return;
    float b0 = sb[0], b1 = sb[1], b2 = sb[2];
    const float4* z = (const float4*)g_z;
    const size_t S = (size_t)NN * (HD_ / 4);
    float4 a = z[i], b = z[S + i], c = z[2 * S + i];
    ((float4*)out)[i] = make_float4(b0 * a.x + b1 * b.x + b2 * c.x,
                                    b0 * a.y + b1 * b.y + b2 * c.y,
                                    b0 * a.z + b1 * b.z + b2 * c.z,
                                    b0 * a.w + b1 * b.w + b2 * c.w);
}

// ================= launcher =================
extern "C" void kernel_launch(void* const* d_in, const int* in_sizes, int n_in,
                              void* d_out, int out_size) {
    const float* h    = (const float*)d_in[0];
    const int*   src  = (const int*)d_in[1];
    const int*   dst  = (const int*)d_in[2];
    const float* W    = (const float*)d_in[3];
    const float* al   = (const float*)d_in[4];
    const float* ar   = (const float*)d_in[5];
    const float* bias = (const float*)d_in[6];
    const float* sW1  = (const float*)d_in[7];
    const float* sb1  = (const float*)d_in[8];
    const float* sW2  = (const float*)d_in[9];
    float* out = (float*)d_out;

    cudaFuncSetAttribute(k_mma_feat, cudaFuncAttributeMaxDynamicSharedMemorySize, F_SMEM_BYTES);
    cudaFuncSetAttribute(k_mma_sem, cudaFuncAttributeMaxDynamicSharedMemorySize, S_SMEM_BYTES);

    const int NTILES = (NN + 127) / 128;   // 157

    k_prep<<<(NN * IN_ + 255) / 256, 256>>>(h, W, sW1);
    k_hist<<<(MM * EE + 255) / 256, 256>>>(dst);

    dim3 gf(NTILES, 2, MM);
    k_mma_feat<<<gf, 256, F_SMEM_BYTES>>>(al, ar);

    dim3 gsc(NSB, MM);
    k_scan1<<<gsc, 256>>>();
    k_scan3<<<gsc, 256>>>();
    k_scatter<<<(MM * EE + 255) / 256, 256>>>(src, dst);
    k_agg<<<(MM * NN * 32 + 255) / 256, 256>>>(bias);

    dim3 gs(NTILES, 1, MM);
    k_mma_sem<<<gs, 256, S_SMEM_BYTES>>>(sb1, sW2);
    k_comb<<<(NN * HD_ / 4 + 255) / 256, 256>>>(out);
}